// round 14
// baseline (speedup 1.0000x reference)
#include <cuda_runtime.h>
#include <math.h>
#include <stdint.h>

// Problem constants
#define NB 64
#define NS 400
#define NV 50000
#define NE 128
#define NH 512
#define NM 512
#define NOOV 20
#define NVO (NV + NOOV)

// Output layout (flattened concatenation of reference outputs)
#define SZ_FD   (NB * NVO)
#define OFF_H   (SZ_FD)
#define OFF_WC  (OFF_H  + NB * NH)
#define OFF_AT  (OFF_WC + NB * NM)
#define OFF_PG  (OFF_AT + NB * NS)
#define OFF_CV  (OFF_PG + NB)
#define TOTAL_OUT (OFF_CV + NB * NS)

// tcgen05 only exists on the 'a' feature targets; the harness also builds a
// plain compute_103 PTX pass which must not see those instructions.
#if !defined(__CUDA_ARCH__) || defined(__CUDA_ARCH_FEAT_SM103_ALL) || defined(__CUDA_ARCH_FEAT_SM100_ALL) || defined(__CUDA_ARCH_FEAT_SM101_ALL)
#define USE_TCGEN05 1
#else
#define USE_TCGEN05 0
#endif

// Scratch (device globals)
__device__ float g_emb[NB * NE];
__device__ float g_gi[NB * 3 * NH];
__device__ float g_gh[NB * 3 * NH];
__device__ float g_h1[NB * NH];
__device__ float g_dec[NB * NH];
__device__ float g_scores[NB * NS];
__device__ float g_attn[NB * NS];
__device__ float g_cat[NB * (NM + NH)];   // [wc | h1]
__device__ float g_hidp[128 * NH];        // hid padded to 128 rows (64..127 = 0)
__device__ float g_pgen[NB];
__device__ float g_sumexp[NB];
__device__ float g_logits[(size_t)NB * NV];   // exp(logit), [b][v]

__device__ __forceinline__ float sigmoidf_(float x) { return 1.0f / (1.0f + expf(-x)); }

// tf32 mma.sync fed raw fp32 bits (HW truncates mantissa to tf32).
__device__ __forceinline__ void mma_tf32(float c[4], unsigned a0, unsigned a1,
                                         unsigned a2, unsigned a3,
                                         unsigned b0, unsigned b1) {
    asm volatile("mma.sync.aligned.m16n8k8.row.col.f32.tf32.tf32.f32 "
                 "{%0,%1,%2,%3}, {%4,%5,%6,%7}, {%8,%9}, {%0,%1,%2,%3};"
                 : "+f"(c[0]), "+f"(c[1]), "+f"(c[2]), "+f"(c[3])
                 : "r"(a0), "r"(a1), "r"(a2), "r"(a3), "r"(b0), "r"(b1));
}
__device__ __forceinline__ void cpa16(float* s, const float* g) {
    unsigned sa = (unsigned)__cvta_generic_to_shared(s);
    asm volatile("cp.async.cg.shared.global [%0], [%1], 16;" :: "r"(sa), "l"(g));
}
__device__ __forceinline__ void cpa16p(float* s, const float* g, bool ok) {
    unsigned sa = (unsigned)__cvta_generic_to_shared(s);
    int sz = ok ? 16 : 0;
    asm volatile("cp.async.cg.shared.global [%0], [%1], 16, %2;" :: "r"(sa), "l"(g), "r"(sz));
}
#define CP_COMMIT() asm volatile("cp.async.commit_group;")
#define CP_WAIT2()  asm volatile("cp.async.wait_group 2;")
#define CP_WAIT1()  asm volatile("cp.async.wait_group 1;")
#define CP_WAIT0()  asm volatile("cp.async.wait_group 0;")

__device__ __forceinline__ unsigned ldb(const float* p) {
    return __float_as_uint(*p);
}

// ---------------- tcgen05 helpers (sm_103a only) ----------------
__device__ __forceinline__ uint32_t smem_u32(const void* p) {
    uint32_t a;
    asm("{ .reg .u64 t; cvta.to.shared.u64 t, %1; cvt.u32.u64 %0, t; }" : "=r"(a) : "l"(p));
    return a;
}
__device__ __forceinline__ uint32_t elect1() {
    uint32_t p;
    asm volatile("{\n\t.reg .pred p;\n\telect.sync _|p, 0xFFFFFFFF;\n\tselp.b32 %0,1,0,p;\n\t}" : "=r"(p));
    return p;
}
#define MB_INIT(a,c) asm volatile("mbarrier.init.shared.b64 [%0], %1;" :: "r"(a), "r"(c) : "memory")
#define MB_INVAL(a)  asm volatile("mbarrier.inval.shared.b64 [%0];" :: "r"(a) : "memory")
__device__ __forceinline__ void mb_wait(uint32_t addr, uint32_t parity) {
    uint32_t done;
    asm volatile("{\n\t.reg .pred p;\n\t"
                 "mbarrier.try_wait.parity.acquire.cta.shared::cta.b64 p, [%1], %2;\n\t"
                 "selp.b32 %0,1,0,p;\n\t}" : "=r"(done) : "r"(addr), "r"(parity) : "memory");
    while (!done) {
        asm volatile("{\n\t.reg .pred p;\n\t"
                     "mbarrier.try_wait.parity.acquire.cta.shared::cta.b64 p, [%1], %2, 0x989680;\n\t"
                     "selp.b32 %0,1,0,p;\n\t}" : "=r"(done) : "r"(addr), "r"(parity) : "memory");
    }
}
#define TCG_ALLOC(sa,n)  asm volatile("tcgen05.alloc.cta_group::1.sync.aligned.shared::cta.b32 [%0], %1;" :: "r"(sa), "r"(n) : "memory")
#define TCG_RELQ()       asm volatile("tcgen05.relinquish_alloc_permit.cta_group::1.sync.aligned;")
#define TCG_DEALLOC(t,n) asm volatile("tcgen05.dealloc.cta_group::1.sync.aligned.b32 %0, %1;" :: "r"(t), "r"(n))
#define TCG_COMMIT(a)    asm volatile("tcgen05.commit.cta_group::1.mbarrier::arrive::one.shared::cluster.b64 [%0];" :: "r"(a) : "memory")
#define TCG_FENCE_AFTER()  asm volatile("tcgen05.fence::after_thread_sync;" ::: "memory")
#define TCG_FENCE_BEFORE() asm volatile("tcgen05.fence::before_thread_sync;" ::: "memory")
#define TCG_WAIT_LD()    asm volatile("tcgen05.wait::ld.sync.aligned;" ::: "memory")
#define FENCE_PA()       asm volatile("fence.proxy.async.shared::cta;" ::: "memory")

#define TCG_LD_X32(r, tmem_addr) \
    asm volatile( \
        "tcgen05.ld.sync.aligned.32x32b.x32.b32 " \
        "{%0, %1, %2, %3, %4, %5, %6, %7, " \
        " %8, %9, %10, %11, %12, %13, %14, %15, " \
        " %16, %17, %18, %19, %20, %21, %22, %23, " \
        " %24, %25, %26, %27, %28, %29, %30, %31}, [%32];" \
        : "=r"((r)[0]),  "=r"((r)[1]),  "=r"((r)[2]),  "=r"((r)[3]), \
          "=r"((r)[4]),  "=r"((r)[5]),  "=r"((r)[6]),  "=r"((r)[7]), \
          "=r"((r)[8]),  "=r"((r)[9]),  "=r"((r)[10]), "=r"((r)[11]), \
          "=r"((r)[12]), "=r"((r)[13]), "=r"((r)[14]), "=r"((r)[15]), \
          "=r"((r)[16]), "=r"((r)[17]), "=r"((r)[18]), "=r"((r)[19]), \
          "=r"((r)[20]), "=r"((r)[21]), "=r"((r)[22]), "=r"((r)[23]), \
          "=r"((r)[24]), "=r"((r)[25]), "=r"((r)[26]), "=r"((r)[27]), \
          "=r"((r)[28]), "=r"((r)[29]), "=r"((r)[30]), "=r"((r)[31]) \
        : "r"(tmem_addr))

// SW128 K-major smem descriptor (layout=2, version=1, SBO=64, LBO=1)
__device__ __forceinline__ uint64_t mk_desc(uint32_t addr) {
    return ((uint64_t)2 << 61) | ((uint64_t)1 << 46) | ((uint64_t)64 << 32)
         | ((uint64_t)1 << 16) | ((uint64_t)(addr >> 4) & 0x3FFF);
}

// idesc: c=F32(1<<4), a=TF32(2<<7), b=TF32(2<<10), N=128 (16<<17), M=128 (8<<24)
#define K2_IDESC ((1u << 4) | (2u << 7) | (2u << 10) | (16u << 17) | (8u << 24))

#if USE_TCGEN05
__device__ __forceinline__ void tcg_mma_tf32(uint32_t d, uint64_t ad, uint64_t bd,
                                             uint32_t id, bool en) {
    uint32_t e = en ? 1u : 0u, z = 0u;
    asm volatile("{\n\t.reg .pred p;\n\tsetp.ne.u32 p, %5, 0;\n\t"
                 "tcgen05.mma.cta_group::1.kind::tf32 [%0], %1, %2, %3, {%4,%4,%4,%4}, p;\n\t}"
                 :: "r"(d), "l"(ad), "l"(bd), "r"(id), "r"(z), "r"(e) : "memory");
}
#endif

// ---------------------------------------------------------------------------
// K0: gather embedding rows, zero score/sumexp scratch + hid padding rows
// ---------------------------------------------------------------------------
__global__ void k0_init(const int* __restrict__ y, const float* __restrict__ emb_W)
{
    int b = blockIdx.x, tid = threadIdx.x;
    int yb = y[b];
    for (int i = tid; i < NE; i += 256) g_emb[b * NE + i] = emb_W[(size_t)yb * NE + i];
    for (int i = tid; i < NH; i += 256) g_hidp[(size_t)(64 + b) * NH + i] = 0.0f;
    if (b == 0 && tid < NB) g_sumexp[tid] = 0.0f;
}

// ---------------------------------------------------------------------------
// Generic small GEMM: C[64, N] = X[64, K] @ W[N, K]^T + bias, tf32 mma.sync.
// ---------------------------------------------------------------------------
#define GLD 36
template<int K>
__global__ __launch_bounds__(256, 1)
void gemm_nt(const float* __restrict__ X, const float* __restrict__ W,
             const float* __restrict__ bias, float* __restrict__ C, int N)
{
    __shared__ float Xs[2][64 * GLD];
    __shared__ float Ws[2][64 * GLD];
    int tid = threadIdx.x, wid = tid >> 5, lane = tid & 31;
    int g = lane >> 2, tig = lane & 3;
    int warp_m = wid & 1, warp_n = wid >> 1;
    int nBase = blockIdx.x * 64;

    float acc[2][2][4];
#pragma unroll
    for (int i = 0; i < 2; i++)
#pragma unroll
        for (int j = 0; j < 2; j++)
#pragma unroll
            for (int q = 0; q < 4; q++) acc[i][j][q] = 0.0f;

    auto load = [&](int s, int k0) {
#pragma unroll
        for (int it = 0; it < 2; it++) {
            int c = tid + it * 256;
            int row = c >> 3, c4 = (c & 7) * 4;
            cpa16(&Xs[s][row * GLD + c4], &X[(size_t)row * K + k0 + c4]);
            cpa16(&Ws[s][row * GLD + c4], &W[(size_t)(nBase + row) * K + k0 + c4]);
        }
    };

    const int NT = K / 32;
    load(0, 0); CP_COMMIT();
    for (int t = 0; t < NT; t++) {
        if (t + 1 < NT) { load((t + 1) & 1, (t + 1) * 32); CP_COMMIT(); CP_WAIT1(); }
        else CP_WAIT0();
        __syncthreads();
        int s = t & 1;
#pragma unroll
        for (int ks = 0; ks < 4; ks++) {
            int kb = ks * 8;
            unsigned bf[2][2];
#pragma unroll
            for (int j = 0; j < 2; j++) {
                int col = warp_n * 16 + j * 8 + g;
                bf[j][0] = ldb(&Ws[s][col * GLD + kb + tig]);
                bf[j][1] = ldb(&Ws[s][col * GLD + kb + tig + 4]);
            }
#pragma unroll
            for (int i = 0; i < 2; i++) {
                int row = warp_m * 32 + i * 16 + g;
                unsigned a0 = ldb(&Xs[s][row * GLD + kb + tig]);
                unsigned a1 = ldb(&Xs[s][(row + 8) * GLD + kb + tig]);
                unsigned a2 = ldb(&Xs[s][row * GLD + kb + tig + 4]);
                unsigned a3 = ldb(&Xs[s][(row + 8) * GLD + kb + tig + 4]);
#pragma unroll
                for (int j = 0; j < 2; j++)
                    mma_tf32(acc[i][j], a0, a1, a2, a3, bf[j][0], bf[j][1]);
            }
        }
        __syncthreads();
    }

#pragma unroll
    for (int i = 0; i < 2; i++) {
        int bb = warp_m * 32 + i * 16 + g;
#pragma unroll
        for (int j = 0; j < 2; j++) {
            int v = nBase + warp_n * 16 + j * 8 + 2 * tig;
            C[(size_t)bb * N + v]           = acc[i][j][0] + bias[v];
            C[(size_t)bb * N + v + 1]       = acc[i][j][1] + bias[v + 1];
            C[(size_t)(bb + 8) * N + v]     = acc[i][j][2] + bias[v];
            C[(size_t)(bb + 8) * N + v + 1] = acc[i][j][3] + bias[v + 1];
        }
    }
}

// ---------------------------------------------------------------------------
// K1b: GRU gate combine (elementwise). grid=64, 512 thr.
// ---------------------------------------------------------------------------
__global__ void k1b_combine(const float* __restrict__ h0g, float* __restrict__ out,
                            int out_size)
{
    int b = blockIdx.x, j = threadIdx.x;
    float gir = g_gi[b * 3 * NH + j];
    float giz = g_gi[b * 3 * NH + NH + j];
    float gin = g_gi[b * 3 * NH + 2 * NH + j];
    float ghr = g_gh[b * 3 * NH + j];
    float ghz = g_gh[b * 3 * NH + NH + j];
    float ghn = g_gh[b * 3 * NH + 2 * NH + j];
    float h0 = h0g[b * NH + j];
    float r = sigmoidf_(gir + ghr);
    float z = sigmoidf_(giz + ghz);
    float n = tanhf(gin + r * ghn);
    float hv = (1.0f - z) * n + z * h0;
    g_h1[b * NH + j] = hv;
    g_cat[b * (NM + NH) + NM + j] = hv;
    if (out_size >= TOTAL_OUT) out[OFF_H + b * NH + j] = hv;
}

// ---------------------------------------------------------------------------
// K2: enc_feat GEMM + fused score epilogue. 128m x 512n x 512k per CTA.
// grid = 200 (m-tiles), 128 thr. B = ALL of Wm (L2-resident), loaded per
// chunk as 512x32; D = 128x512 fp32 in 512 TMEM cols. Scores stored directly
// (no atomics). 2-stage cp.async ring (smem 161KB).
// ---------------------------------------------------------------------------
#define K2_A_OFF 1024
#define K2_STG   (16384 + 65536)            // A 16KB + B 64KB per stage
#define K2_B_OFF(s) (K2_A_OFF + (s) * K2_STG + 16384)
#define K2_A_ST(s)  (K2_A_OFF + (s) * K2_STG)
#define K2_SMEM  (1024 + 2 * K2_STG)        // 164864

__global__ __launch_bounds__(128, 1)
void k2_tc(const float* __restrict__ MB, const float* __restrict__ Wm,
           const float* __restrict__ Wc, const float* __restrict__ av,
           const float* __restrict__ cov)
{
    extern __shared__ char smem[];
    int tid = threadIdx.x, wid = tid >> 5;
    int mBase = blockIdx.x * 128;
    const int NT = NM / 32;   // 16 chunks

    // load chunk u: A 128x32 (MB rows), B 512x32 (all Wm rows), SW128 rows
    auto loadc = [&](int u) {
        int s = u & 1;
        int k0 = u * 32;
        char* abase = smem + K2_A_ST(s);
        char* bbase = smem + K2_B_OFF(s);
#pragma unroll
        for (int i = 0; i < 8; i++) {       // A: 1024 16B chunks
            int idx = tid + i * 128;
            int row = idx >> 3, c = idx & 7;
            uint32_t boff = row * 128 + c * 16;
            uint32_t sw = boff ^ ((boff >> 3) & 0x70);
            cpa16((float*)(abase + sw), &MB[(size_t)(mBase + row) * NM + k0 + c * 4]);
        }
#pragma unroll
        for (int i = 0; i < 32; i++) {      // B: 4096 16B chunks
            int idx = tid + i * 128;
            int row = idx >> 3, c = idx & 7;
            uint32_t boff = row * 128 + c * 16;
            uint32_t sw = boff ^ ((boff >> 3) & 0x70);
            cpa16((float*)(bbase + sw), &Wm[(size_t)row * NM + k0 + c * 4]);
        }
        CP_COMMIT();
    };

#if USE_TCGEN05
    uint32_t sb = smem_u32(smem);
    if (wid == 0) { TCG_ALLOC(sb, 512); TCG_RELQ(); }
    if (tid == 0) { MB_INIT(sb + 8, 1); MB_INIT(sb + 16, 1); }
    __syncthreads();
    uint32_t tmem;
    asm volatile("ld.shared.b32 %0, [%1];" : "=r"(tmem) : "r"(sb));

    loadc(0); loadc(1);

    for (int t = 0; t < NT; t++) {
        if (t <= NT - 2) CP_WAIT1();
        else CP_WAIT0();
        FENCE_PA();
        __syncthreads();
        if (wid == 0) {
            TCG_FENCE_AFTER();
            if (elect1()) {
                int s = t & 1;
                uint64_t ad = mk_desc(sb + K2_A_ST(s));
#pragma unroll
                for (int n = 0; n < 4; n++) {
                    uint64_t bd = mk_desc(sb + K2_B_OFF(s) + n * 16384);
#pragma unroll
                    for (int k = 0; k < 4; k++)
                        tcg_mma_tf32(tmem + n * 128, ad + k * 2, bd + k * 2,
                                     K2_IDESC, !(t == 0 && k == 0));
                }
                TCG_COMMIT(sb + 8 + (t & 1) * 8);
            }
        }
        int u = t + 2;
        if (u < NT) {
            // slot u&1 freed when MMA of chunk u-2 committed; phase u/2-1
            mb_wait(sb + 8 + (u & 1) * 8, ((u >> 1) - 1) & 1);
            loadc(u);
        }
    }
    // final commit t=15 on slot 1: 8th arrival -> phase 7 -> parity 1.
    mb_wait(sb + 16, 1);
    TCG_FENCE_AFTER();

    // epilogue: thread owns row tid; 512 cols in 16 LDTM blocks; direct store
    int gr = mBase + tid;
    int bb = gr / NS;
    int srow = gr - bb * NS;
    float cv = cov[bb * NS + srow];
    const float* decb = g_dec + bb * NH;
    float partial = 0.0f;
#pragma unroll
    for (int blk = 0; blk < 16; blk++) {
        uint32_t d32[32];
        TCG_LD_X32(d32, tmem + blk * 32);
        TCG_WAIT_LD();
#pragma unroll
        for (int j = 0; j < 32; j++) {
            int hc = blk * 32 + j;
            float x = __uint_as_float(d32[j]) + decb[hc] + cv * Wc[hc];
            partial += av[hc] * tanhf(x);
        }
    }
    g_scores[gr] = partial;
    TCG_FENCE_BEFORE();
    __syncthreads();
    if (tid == 0) { MB_INVAL(sb + 8); MB_INVAL(sb + 16); }
    __syncthreads();
    if (wid == 0) TCG_DEALLOC(tmem, 512);

#else   // scalar fallback (correct, never runs on GB300)
    int gr = mBase + tid;
    int bb = gr / NS;
    int srow = gr - bb * NS;
    float cv = cov[bb * NS + srow];
    const float* mrow = MB + (size_t)gr * NM;
    const float* decb = g_dec + bb * NH;
    float partial = 0.0f;
    for (int hc = 0; hc < NH; hc++) {
        float acc = 0.0f;
        const float* wrow = Wm + (size_t)hc * NM;
        for (int k = 0; k < NM; k++) acc += mrow[k] * wrow[k];
        partial += av[hc] * tanhf(acc + decb[hc] + cv * Wc[hc]);
    }
    g_scores[gr] = partial;
#endif
}

// ---------------------------------------------------------------------------
// K3: masked softmax, coverage, word_context, p_gen. grid=64, 512 thr.
// ---------------------------------------------------------------------------
__global__ void k3_attn(const float* __restrict__ MB, const float* __restrict__ mask,
                        const float* __restrict__ cov,
                        const int* __restrict__ y, const float* __restrict__ emb_W,
                        const float* __restrict__ pgen_W, const float* __restrict__ pgen_b,
                        float* __restrict__ out, int out_size)
{
    int b = blockIdx.x, tid = threadIdx.x;
    bool full = (out_size >= TOTAL_OUT);
    __shared__ float sc[NS];
    __shared__ float att[NS];
    __shared__ float red[512];
    __shared__ float wcs[NM];

    for (int i = tid; i < NS; i += 512) {
        float m = mask[b * NS + i];
        sc[i] = (m > 0.0f) ? g_scores[b * NS + i] : -1e9f;
    }
    __syncthreads();

    float mx = -1e30f;
    for (int i = tid; i < NS; i += 512) mx = fmaxf(mx, sc[i]);
    red[tid] = mx; __syncthreads();
    for (int o = 256; o > 0; o >>= 1) { if (tid < o) red[tid] = fmaxf(red[tid], red[tid + o]); __syncthreads(); }
    mx = red[0]; __syncthreads();

    float sm = 0.0f;
    for (int i = tid; i < NS; i += 512) { float e = expf(sc[i] - mx); sc[i] = e; sm += e; }
    red[tid] = sm; __syncthreads();
    for (int o = 256; o > 0; o >>= 1) { if (tid < o) red[tid] += red[tid + o]; __syncthreads(); }
    sm = red[0]; __syncthreads();

    float s2 = 0.0f;
    for (int i = tid; i < NS; i += 512) {
        float m = mask[b * NS + i];
        float a = sc[i] / sm * m;
        att[i] = a; s2 += a;
    }
    red[tid] = s2; __syncthreads();
    for (int o = 256; o > 0; o >>= 1) { if (tid < o) red[tid] += red[tid + o]; __syncthreads(); }
    s2 = red[0]; __syncthreads();
    float inv = 1.0f / (s2 + 1e-10f);
    for (int i = tid; i < NS; i += 512) {
        float a = att[i] * inv;
        att[i] = a;
        g_attn[b * NS + i] = a;
        if (full) {
            out[OFF_AT + b * NS + i] = a;
            out[OFF_CV + b * NS + i] = cov[b * NS + i] + a;
        }
    }
    __syncthreads();

    {
        float a0 = 0.f, a1 = 0.f, a2 = 0.f, a3 = 0.f;
        const float* mbb = MB + (size_t)b * NS * NM + tid;
#pragma unroll 4
        for (int s = 0; s < NS; s += 4) {
            a0 += att[s]     * mbb[(size_t)s * NM];
            a1 += att[s + 1] * mbb[(size_t)(s + 1) * NM];
            a2 += att[s + 2] * mbb[(size_t)(s + 2) * NM];
            a3 += att[s + 3] * mbb[(size_t)(s + 3) * NM];
        }
        float a = (a0 + a1) + (a2 + a3);
        wcs[tid] = a;
        g_cat[b * (NM + NH) + tid] = a;
        if (full) out[OFF_WC + b * NM + tid] = a;
    }
    __syncthreads();

    int yb = y[b];
    float ps = 0.0f;
    for (int i = tid; i < NM + NH + NE; i += 512) {
        float xv = (i < NM) ? wcs[i]
                 : (i < NM + NH) ? g_h1[b * NH + (i - NM)]
                 : emb_W[(size_t)yb * NE + (i - NM - NH)];
        ps += pgen_W[i] * xv;
    }
    red[tid] = ps; __syncthreads();
    for (int o = 256; o > 0; o >>= 1) { if (tid < o) red[tid] += red[tid + o]; __syncthreads(); }
    if (tid == 0) {
        float p = sigmoidf_(red[0] + pgen_b[0]);
        g_pgen[b] = p;
        if (full) out[OFF_PG + b] = p;
    }
}

// ---------------------------------------------------------------------------
// K4a: vocab logits on tcgen05. D[128 vocab, 128 pad-b] = W2tile @ hidp^T.
// Epilogue: smem tile + simple column sums; g_logits in [b][v] layout.
// (validated round 13)
// ---------------------------------------------------------------------------
#define K4_A_OFF 1024
#define K4_B_OFF (1024 + 3 * 16384)
#define K4_SMEM  (1024 + 6 * 16384)   // 99328
#define ES_LD 65

__global__ __launch_bounds__(128, 1)
void k4a_tc(const float* __restrict__ W2, const float* __restrict__ b2)
{
    extern __shared__ char smem[];
    int tid = threadIdx.x, wid = tid >> 5;
    int vBase = blockIdx.x * 128;
    const int NT = NH / 32;   // 16 chunks

    auto loadc = [&](int u) {
        int s = u % 3;
        int k0 = u * 32;
        char* abase = smem + K4_A_OFF + s * 16384;
        char* bbase = smem + K4_B_OFF + s * 16384;
#pragma unroll
        for (int i = 0; i < 8; i++) {
            int idx = tid + i * 128;
            int row = idx >> 3, c = idx & 7;
            uint32_t boff = row * 128 + c * 16;
            uint32_t sw = boff ^ ((boff >> 3) & 0x70);
            int vr = vBase + row;
            cpa16p((float*)(abase + sw), &W2[(size_t)vr * NH + k0 + c * 4], vr < NV);
        }
#pragma unroll
        for (int i = 0; i < 8; i++) {
            int idx = tid + i * 128;
            int row = idx >> 3, c = idx & 7;
            uint32_t boff = row * 128 + c * 16;
            uint32_t sw = boff ^ ((boff >> 3) & 0x70);
            cpa16((float*)(bbase + sw), &g_hidp[(size_t)row * NH + k0 + c * 4]);
        }
        CP_COMMIT();
    };

#if USE_TCGEN05
    uint32_t sb = smem_u32(smem);
    if (wid == 0) { TCG_ALLOC(sb, 128); TCG_RELQ(); }
    if (tid == 0) { MB_INIT(sb + 8, 1); MB_INIT(sb + 16, 1); MB_INIT(sb + 24, 1); }
    __syncthreads();
    uint32_t tmem;
    asm volatile("ld.shared.b32 %0, [%1];" : "=r"(tmem) : "r"(sb));

    loadc(0); loadc(1); loadc(2);

    for (int t = 0; t < NT; t++) {
        if (t <= NT - 3) CP_WAIT2();
        else if (t == NT - 2) CP_WAIT1();
        else CP_WAIT0();
        FENCE_PA();
        __syncthreads();
        if (wid == 0) {
            TCG_FENCE_AFTER();
            if (elect1()) {
                int s = t % 3;
                uint64_t ad = mk_desc(sb + K4_A_OFF + s * 16384);
                uint64_t bd = mk_desc(sb + K4_B_OFF + s * 16384);
#pragma unroll
                for (int k = 0; k < 4; k++)
                    tcg_mma_tf32(tmem, ad + k * 2, bd + k * 2, K2_IDESC, !(t == 0 && k == 0));
                TCG_COMMIT(sb + 8 + (t % 3) * 8);
            }
        }
        int u = t + 3;
        if (u < NT) {
            mb_wait(sb + 8 + (u % 3) * 8, ((u / 3) - 1) & 1);
            loadc(u);
        }
    }
    mb_wait(sb + 8, 1);
    TCG_FENCE_AFTER();
    __syncthreads();

    float* es = (float*)(smem + K4_A_OFF);
    int v = vBase + tid;
    bool valid = (v < NV);
    float bias = valid ? b2[v] : 0.0f;
    {
        uint32_t d0[32];
        TCG_LD_X32(d0, tmem);
        TCG_WAIT_LD();
#pragma unroll
        for (int j = 0; j < 32; j++)
            es[tid * ES_LD + j] = valid ? expf(__uint_as_float(d0[j]) + bias) : 0.0f;
    }
    {
        uint32_t d1[32];
        TCG_LD_X32(d1, tmem + 32);
        TCG_WAIT_LD();
#pragma unroll
        for (int j = 0; j < 32; j++)
            es[tid * ES_LD + 32 + j] = valid ? expf(__uint_as_float(d1[j]) + bias) : 0.0f;
    }
    TCG_FENCE_BEFORE();
    __syncthreads();

    if (tid < 64) {
        float s = 0.0f;
#pragma unroll 8
        for (int r = 0; r < 128; r++) s += es[r * ES_LD + tid];
        atomicAdd(&g_sumexp[tid], s);
    }
    if (valid) {
#pragma unroll 4
        for (int b = 0; b < NB; b++)
            g_logits[(size_t)b * NV + v] = es[tid * ES_LD + b];
    }
    __syncthreads();
    if (tid == 0) { MB_INVAL(sb + 8); MB_INVAL(sb + 16); MB_INVAL(sb + 24); }
    __syncthreads();
    if (wid == 0) TCG_DEALLOC(tmem, 128);

#else   // scalar fallback
    int v = vBase + tid;
    if (v < NV) {
        float bias = b2[v];
        float s[NB];
        for (int b = 0; b < NB; b++) {
            float acc = bias;
            for (int k = 0; k < NH; k++)
                acc += W2[(size_t)v * NH + k] * g_hidp[(size_t)b * NH + k];
            s[b] = expf(acc);
            g_logits[(size_t)b * NV + v] = s[b];
        }
        for (int b = 0; b < NB; b++) atomicAdd(&g_sumexp[b], s[b]);
    }
#endif
}

// ---------------------------------------------------------------------------
// K4b: normalize + write final vocab part. grid=(64, 8), 256 thr.
// ---------------------------------------------------------------------------
#define VCHUNK 6250
__global__ void k4b_norm(float* __restrict__ out)
{
    int b = blockIdx.x, ch = blockIdx.y, tid = threadIdx.x;
    float scale = g_pgen[b] / g_sumexp[b];
    const float* lg = &g_logits[(size_t)b * NV];
    float* orow = out + (size_t)b * NVO;
    int v0 = ch * VCHUNK;
    for (int v = v0 + tid * 2; v < v0 + VCHUNK; v += 512) {
        float2 e = *(const float2*)&lg[v];
        e.x *= scale; e.y *= scale;
        *(float2*)&orow[v] = e;
    }
    if (ch == 0) {
        for (int v = NV + tid; v < NVO; v += 256) orow[v] = 0.0f;
    }
}

// ---------------------------------------------------------------------------
// K4c: OOV pointer scatter. grid=64, 400 thr.
// ---------------------------------------------------------------------------
__global__ void k4c_scatter(const int* __restrict__ src_oov, float* __restrict__ out)
{
    int b = blockIdx.x, s = threadIdx.x;
    float q = 1.0f - g_pgen[b];
    float* orow = out + (size_t)b * NVO;
    atomicAdd(&orow[src_oov[b * NS + s]], q * g_attn[b * NS + s]);
}

// ---------------------------------------------------------------------------
extern "C" void kernel_launch(void* const* d_in, const int* in_sizes, int n_in,
                              void* d_out, int out_size)
{
    int sh = (n_in >= 23) ? 1 : 0;
    const int*   y        = (const int*)  d_in[0];
    const float* h0g      = (const float*)d_in[1];
    const float* MB       = (const float*)d_in[2];
    const float* mask     = (const float*)d_in[3];
    const int*   src_oov  = (const int*)  d_in[4 + sh];
    const float* cov      = (const float*)d_in[5 + sh];
    const float* emb_W    = (const float*)d_in[6 + sh];
    const float* Wih      = (const float*)d_in[7 + sh];
    const float* Whh      = (const float*)d_in[8 + sh];
    const float* bih      = (const float*)d_in[9 + sh];
    const float* bhh      = (const float*)d_in[10 + sh];
    const float* Wm       = (const float*)d_in[11 + sh];
    const float* Wd       = (const float*)d_in[12 + sh];
    const float* bd       = (const float*)d_in[13 + sh];
    const float* Wc       = (const float*)d_in[14 + sh];
    const float* av       = (const float*)d_in[15 + sh];
    const float* pgen_W   = (const float*)d_in[16 + sh];
    const float* pgen_b   = (const float*)d_in[17 + sh];
    const float* vd1_W    = (const float*)d_in[18 + sh];
    const float* vd1_b    = (const float*)d_in[19 + sh];
    const float* W2       = (const float*)d_in[20 + sh];
    const float* b2       = (const float*)d_in[21 + sh];
    float* out = (float*)d_out;

    float *p_emb, *p_gi, *p_gh, *p_h1, *p_dec, *p_cat, *p_hidp;
    cudaGetSymbolAddress((void**)&p_emb,  g_emb);
    cudaGetSymbolAddress((void**)&p_gi,   g_gi);
    cudaGetSymbolAddress((void**)&p_gh,   g_gh);
    cudaGetSymbolAddress((void**)&p_h1,   g_h1);
    cudaGetSymbolAddress((void**)&p_dec,  g_dec);
    cudaGetSymbolAddress((void**)&p_cat,  g_cat);
    cudaGetSymbolAddress((void**)&p_hidp, g_hidp);

    cudaFuncSetAttribute(k2_tc,  cudaFuncAttributeMaxDynamicSharedMemorySize, K2_SMEM);
    cudaFuncSetAttribute(k4a_tc, cudaFuncAttributeMaxDynamicSharedMemorySize, K4_SMEM);

    k0_init<<<NB, 256>>>(y, emb_W);

    gemm_nt<128><<<3 * NH / 64, 256>>>(p_emb, Wih, bih, p_gi, 3 * NH);   // gi
    gemm_nt<512><<<3 * NH / 64, 256>>>(h0g,   Whh, bhh, p_gh, 3 * NH);   // gh
    k1b_combine<<<NB, 512>>>(h0g, out, out_size);
    gemm_nt<512><<<NH / 64, 256>>>(p_h1, Wd, bd, p_dec, NH);             // dec_feat

    k2_tc<<<(NB * NS) / 128, 128, K2_SMEM>>>(MB, Wm, Wc, av, cov);       // 200 CTAs

    k3_attn<<<NB, 512>>>(MB, mask, cov, y, emb_W, pgen_W, pgen_b, out, out_size);

    gemm_nt<1024><<<NH / 64, 256>>>(p_cat, vd1_W, vd1_b, p_hidp, NH);    // vd1

    k4a_tc<<<(NV + 127) / 128, 128, K4_SMEM>>>(W2, b2);

    dim3 g4b(NB, 8);
    k4b_norm<<<g4b, 256>>>(out);
    k4c_scatter<<<NB, NS>>>(src_oov, out);
}

// round 15
// speedup vs baseline: 1.5100x; 1.5100x over previous
#include <cuda_runtime.h>
#include <math.h>
#include <stdint.h>

// Problem constants
#define NB 64
#define NS 400
#define NV 50000
#define NE 128
#define NH 512
#define NM 512
#define NOOV 20
#define NVO (NV + NOOV)

// Output layout (flattened concatenation of reference outputs)
#define SZ_FD   (NB * NVO)
#define OFF_H   (SZ_FD)
#define OFF_WC  (OFF_H  + NB * NH)
#define OFF_AT  (OFF_WC + NB * NM)
#define OFF_PG  (OFF_AT + NB * NS)
#define OFF_CV  (OFF_PG + NB)
#define TOTAL_OUT (OFF_CV + NB * NS)

// tcgen05 only exists on the 'a' feature targets; the harness also builds a
// plain compute_103 PTX pass which must not see those instructions.
#if !defined(__CUDA_ARCH__) || defined(__CUDA_ARCH_FEAT_SM103_ALL) || defined(__CUDA_ARCH_FEAT_SM100_ALL) || defined(__CUDA_ARCH_FEAT_SM101_ALL)
#define USE_TCGEN05 1
#else
#define USE_TCGEN05 0
#endif

// Scratch (device globals)
__device__ float g_emb[NB * NE];
__device__ float g_gi[NB * 3 * NH];
__device__ float g_gh[NB * 3 * NH];
__device__ float g_h1[NB * NH];
__device__ float g_dec[NB * NH];
__device__ float g_scores[NB * NS];
__device__ float g_attn[NB * NS];
__device__ float g_cat[NB * (NM + NH)];   // [wc | h1]
__device__ float g_hidp[128 * NH];        // hid padded to 128 rows (64..127 = 0)
__device__ float g_pgen[NB];
__device__ float g_sumexp[NB];
__device__ float g_logits[(size_t)NB * NV];   // exp(logit), [b][v]

__device__ __forceinline__ float sigmoidf_(float x) { return 1.0f / (1.0f + expf(-x)); }

// tf32 mma.sync fed raw fp32 bits (HW truncates mantissa to tf32).
__device__ __forceinline__ void mma_tf32(float c[4], unsigned a0, unsigned a1,
                                         unsigned a2, unsigned a3,
                                         unsigned b0, unsigned b1) {
    asm volatile("mma.sync.aligned.m16n8k8.row.col.f32.tf32.tf32.f32 "
                 "{%0,%1,%2,%3}, {%4,%5,%6,%7}, {%8,%9}, {%0,%1,%2,%3};"
                 : "+f"(c[0]), "+f"(c[1]), "+f"(c[2]), "+f"(c[3])
                 : "r"(a0), "r"(a1), "r"(a2), "r"(a3), "r"(b0), "r"(b1));
}
__device__ __forceinline__ void cpa16(float* s, const float* g) {
    unsigned sa = (unsigned)__cvta_generic_to_shared(s);
    asm volatile("cp.async.cg.shared.global [%0], [%1], 16;" :: "r"(sa), "l"(g));
}
__device__ __forceinline__ void cpa16p(float* s, const float* g, bool ok) {
    unsigned sa = (unsigned)__cvta_generic_to_shared(s);
    int sz = ok ? 16 : 0;
    asm volatile("cp.async.cg.shared.global [%0], [%1], 16, %2;" :: "r"(sa), "l"(g), "r"(sz));
}
#define CP_COMMIT() asm volatile("cp.async.commit_group;")
#define CP_WAIT2()  asm volatile("cp.async.wait_group 2;")
#define CP_WAIT1()  asm volatile("cp.async.wait_group 1;")
#define CP_WAIT0()  asm volatile("cp.async.wait_group 0;")

__device__ __forceinline__ unsigned ldb(const float* p) {
    return __float_as_uint(*p);
}

// ---------------- tcgen05 helpers (sm_103a only) ----------------
__device__ __forceinline__ uint32_t smem_u32(const void* p) {
    uint32_t a;
    asm("{ .reg .u64 t; cvta.to.shared.u64 t, %1; cvt.u32.u64 %0, t; }" : "=r"(a) : "l"(p));
    return a;
}
__device__ __forceinline__ uint32_t elect1() {
    uint32_t p;
    asm volatile("{\n\t.reg .pred p;\n\telect.sync _|p, 0xFFFFFFFF;\n\tselp.b32 %0,1,0,p;\n\t}" : "=r"(p));
    return p;
}
#define MB_INIT(a,c) asm volatile("mbarrier.init.shared.b64 [%0], %1;" :: "r"(a), "r"(c) : "memory")
#define MB_INVAL(a)  asm volatile("mbarrier.inval.shared.b64 [%0];" :: "r"(a) : "memory")
__device__ __forceinline__ void mb_wait(uint32_t addr, uint32_t parity) {
    uint32_t done;
    asm volatile("{\n\t.reg .pred p;\n\t"
                 "mbarrier.try_wait.parity.acquire.cta.shared::cta.b64 p, [%1], %2;\n\t"
                 "selp.b32 %0,1,0,p;\n\t}" : "=r"(done) : "r"(addr), "r"(parity) : "memory");
    while (!done) {
        asm volatile("{\n\t.reg .pred p;\n\t"
                     "mbarrier.try_wait.parity.acquire.cta.shared::cta.b64 p, [%1], %2, 0x989680;\n\t"
                     "selp.b32 %0,1,0,p;\n\t}" : "=r"(done) : "r"(addr), "r"(parity) : "memory");
    }
}
#define TCG_ALLOC(sa,n)  asm volatile("tcgen05.alloc.cta_group::1.sync.aligned.shared::cta.b32 [%0], %1;" :: "r"(sa), "r"(n) : "memory")
#define TCG_RELQ()       asm volatile("tcgen05.relinquish_alloc_permit.cta_group::1.sync.aligned;")
#define TCG_DEALLOC(t,n) asm volatile("tcgen05.dealloc.cta_group::1.sync.aligned.b32 %0, %1;" :: "r"(t), "r"(n))
#define TCG_COMMIT(a)    asm volatile("tcgen05.commit.cta_group::1.mbarrier::arrive::one.shared::cluster.b64 [%0];" :: "r"(a) : "memory")
#define TCG_FENCE_AFTER()  asm volatile("tcgen05.fence::after_thread_sync;" ::: "memory")
#define TCG_FENCE_BEFORE() asm volatile("tcgen05.fence::before_thread_sync;" ::: "memory")
#define TCG_WAIT_LD()    asm volatile("tcgen05.wait::ld.sync.aligned;" ::: "memory")
#define FENCE_PA()       asm volatile("fence.proxy.async.shared::cta;" ::: "memory")

#define TCG_LD_X32(r, tmem_addr) \
    asm volatile( \
        "tcgen05.ld.sync.aligned.32x32b.x32.b32 " \
        "{%0, %1, %2, %3, %4, %5, %6, %7, " \
        " %8, %9, %10, %11, %12, %13, %14, %15, " \
        " %16, %17, %18, %19, %20, %21, %22, %23, " \
        " %24, %25, %26, %27, %28, %29, %30, %31}, [%32];" \
        : "=r"((r)[0]),  "=r"((r)[1]),  "=r"((r)[2]),  "=r"((r)[3]), \
          "=r"((r)[4]),  "=r"((r)[5]),  "=r"((r)[6]),  "=r"((r)[7]), \
          "=r"((r)[8]),  "=r"((r)[9]),  "=r"((r)[10]), "=r"((r)[11]), \
          "=r"((r)[12]), "=r"((r)[13]), "=r"((r)[14]), "=r"((r)[15]), \
          "=r"((r)[16]), "=r"((r)[17]), "=r"((r)[18]), "=r"((r)[19]), \
          "=r"((r)[20]), "=r"((r)[21]), "=r"((r)[22]), "=r"((r)[23]), \
          "=r"((r)[24]), "=r"((r)[25]), "=r"((r)[26]), "=r"((r)[27]), \
          "=r"((r)[28]), "=r"((r)[29]), "=r"((r)[30]), "=r"((r)[31]) \
        : "r"(tmem_addr))

// SW128 K-major smem descriptor (layout=2, version=1, SBO=64, LBO=1)
__device__ __forceinline__ uint64_t mk_desc(uint32_t addr) {
    return ((uint64_t)2 << 61) | ((uint64_t)1 << 46) | ((uint64_t)64 << 32)
         | ((uint64_t)1 << 16) | ((uint64_t)(addr >> 4) & 0x3FFF);
}

// idesc: c=F32(1<<4), a=TF32(2<<7), b=TF32(2<<10), N=128 (16<<17), M=128 (8<<24)
#define K2_IDESC ((1u << 4) | (2u << 7) | (2u << 10) | (16u << 17) | (8u << 24))

#if USE_TCGEN05
__device__ __forceinline__ void tcg_mma_tf32(uint32_t d, uint64_t ad, uint64_t bd,
                                             uint32_t id, bool en) {
    uint32_t e = en ? 1u : 0u, z = 0u;
    asm volatile("{\n\t.reg .pred p;\n\tsetp.ne.u32 p, %5, 0;\n\t"
                 "tcgen05.mma.cta_group::1.kind::tf32 [%0], %1, %2, %3, {%4,%4,%4,%4}, p;\n\t}"
                 :: "r"(d), "l"(ad), "l"(bd), "r"(id), "r"(z), "r"(e) : "memory");
}
#endif

// ---------------------------------------------------------------------------
// K0: gather embedding rows, zero score/sumexp scratch + hid padding rows
// ---------------------------------------------------------------------------
__global__ void k0_init(const int* __restrict__ y, const float* __restrict__ emb_W)
{
    int b = blockIdx.x, tid = threadIdx.x;
    int yb = y[b];
    for (int i = tid; i < NE; i += 256) g_emb[b * NE + i] = emb_W[(size_t)yb * NE + i];
    for (int i = tid; i < NS; i += 256) g_scores[b * NS + i] = 0.0f;
    for (int i = tid; i < NH; i += 256) g_hidp[(size_t)(64 + b) * NH + i] = 0.0f;
    if (b == 0 && tid < NB) g_sumexp[tid] = 0.0f;
}

// ---------------------------------------------------------------------------
// Generic small GEMM: C[64, N] = X[64, K] @ W[N, K]^T + bias, tf32 mma.sync.
// ---------------------------------------------------------------------------
#define GLD 36
template<int K>
__global__ __launch_bounds__(256, 1)
void gemm_nt(const float* __restrict__ X, const float* __restrict__ W,
             const float* __restrict__ bias, float* __restrict__ C, int N)
{
    __shared__ float Xs[2][64 * GLD];
    __shared__ float Ws[2][64 * GLD];
    int tid = threadIdx.x, wid = tid >> 5, lane = tid & 31;
    int g = lane >> 2, tig = lane & 3;
    int warp_m = wid & 1, warp_n = wid >> 1;
    int nBase = blockIdx.x * 64;

    float acc[2][2][4];
#pragma unroll
    for (int i = 0; i < 2; i++)
#pragma unroll
        for (int j = 0; j < 2; j++)
#pragma unroll
            for (int q = 0; q < 4; q++) acc[i][j][q] = 0.0f;

    auto load = [&](int s, int k0) {
#pragma unroll
        for (int it = 0; it < 2; it++) {
            int c = tid + it * 256;
            int row = c >> 3, c4 = (c & 7) * 4;
            cpa16(&Xs[s][row * GLD + c4], &X[(size_t)row * K + k0 + c4]);
            cpa16(&Ws[s][row * GLD + c4], &W[(size_t)(nBase + row) * K + k0 + c4]);
        }
    };

    const int NT = K / 32;
    load(0, 0); CP_COMMIT();
    for (int t = 0; t < NT; t++) {
        if (t + 1 < NT) { load((t + 1) & 1, (t + 1) * 32); CP_COMMIT(); CP_WAIT1(); }
        else CP_WAIT0();
        __syncthreads();
        int s = t & 1;
#pragma unroll
        for (int ks = 0; ks < 4; ks++) {
            int kb = ks * 8;
            unsigned bf[2][2];
#pragma unroll
            for (int j = 0; j < 2; j++) {
                int col = warp_n * 16 + j * 8 + g;
                bf[j][0] = ldb(&Ws[s][col * GLD + kb + tig]);
                bf[j][1] = ldb(&Ws[s][col * GLD + kb + tig + 4]);
            }
#pragma unroll
            for (int i = 0; i < 2; i++) {
                int row = warp_m * 32 + i * 16 + g;
                unsigned a0 = ldb(&Xs[s][row * GLD + kb + tig]);
                unsigned a1 = ldb(&Xs[s][(row + 8) * GLD + kb + tig]);
                unsigned a2 = ldb(&Xs[s][row * GLD + kb + tig + 4]);
                unsigned a3 = ldb(&Xs[s][(row + 8) * GLD + kb + tig + 4]);
#pragma unroll
                for (int j = 0; j < 2; j++)
                    mma_tf32(acc[i][j], a0, a1, a2, a3, bf[j][0], bf[j][1]);
            }
        }
        __syncthreads();
    }

#pragma unroll
    for (int i = 0; i < 2; i++) {
        int bb = warp_m * 32 + i * 16 + g;
#pragma unroll
        for (int j = 0; j < 2; j++) {
            int v = nBase + warp_n * 16 + j * 8 + 2 * tig;
            C[(size_t)bb * N + v]           = acc[i][j][0] + bias[v];
            C[(size_t)bb * N + v + 1]       = acc[i][j][1] + bias[v + 1];
            C[(size_t)(bb + 8) * N + v]     = acc[i][j][2] + bias[v];
            C[(size_t)(bb + 8) * N + v + 1] = acc[i][j][3] + bias[v + 1];
        }
    }
}

// ---------------------------------------------------------------------------
// K1b: GRU gate combine (elementwise). grid=64, 512 thr.
// ---------------------------------------------------------------------------
__global__ void k1b_combine(const float* __restrict__ h0g, float* __restrict__ out,
                            int out_size)
{
    int b = blockIdx.x, j = threadIdx.x;
    float gir = g_gi[b * 3 * NH + j];
    float giz = g_gi[b * 3 * NH + NH + j];
    float gin = g_gi[b * 3 * NH + 2 * NH + j];
    float ghr = g_gh[b * 3 * NH + j];
    float ghz = g_gh[b * 3 * NH + NH + j];
    float ghn = g_gh[b * 3 * NH + 2 * NH + j];
    float h0 = h0g[b * NH + j];
    float r = sigmoidf_(gir + ghr);
    float z = sigmoidf_(giz + ghz);
    float n = tanhf(gin + r * ghn);
    float hv = (1.0f - z) * n + z * h0;
    g_h1[b * NH + j] = hv;
    g_cat[b * (NM + NH) + NM + j] = hv;
    if (out_size >= TOTAL_OUT) out[OFF_H + b * NH + j] = hv;
}

// ---------------------------------------------------------------------------
// K2: enc_feat GEMM + fused score epilogue. 128x128x512 per CTA, 128 thr.
// grid (4 n-blocks, 200 m-blocks). tcgen05 tf32 SS path (round-13 proven).
// ---------------------------------------------------------------------------
#define K2_A_OFF 1024
#define K2_B_OFF (1024 + 3 * 16384)
#define K2_SMEM  (1024 + 6 * 16384)   // 99328

__global__ __launch_bounds__(128, 1)
void k2_tc(const float* __restrict__ MB, const float* __restrict__ Wm,
           const float* __restrict__ Wc, const float* __restrict__ av,
           const float* __restrict__ cov)
{
    extern __shared__ char smem[];
    int tid = threadIdx.x, wid = tid >> 5, lane = tid & 31;
    int mBase = blockIdx.y * 128, nBase = blockIdx.x * 128;
    const int NT = NM / 32;   // 16 chunks

    auto loadc = [&](int u) {
        int s = u % 3;
        int k0 = u * 32;
        char* abase = smem + K2_A_OFF + s * 16384;
        char* bbase = smem + K2_B_OFF + s * 16384;
#pragma unroll
        for (int i = 0; i < 8; i++) {
            int idx = tid + i * 128;
            int row = idx >> 3, c = idx & 7;
            uint32_t boff = row * 128 + c * 16;
            uint32_t sw = boff ^ ((boff >> 3) & 0x70);
            cpa16((float*)(abase + sw), &MB[(size_t)(mBase + row) * NM + k0 + c * 4]);
            cpa16((float*)(bbase + sw), &Wm[(size_t)(nBase + row) * NM + k0 + c * 4]);
        }
        CP_COMMIT();
    };

#if USE_TCGEN05
    uint32_t sb = smem_u32(smem);
    if (wid == 0) { TCG_ALLOC(sb, 128); TCG_RELQ(); }
    if (tid == 0) { MB_INIT(sb + 8, 1); MB_INIT(sb + 16, 1); MB_INIT(sb + 24, 1); }
    __syncthreads();
    uint32_t tmem;
    asm volatile("ld.shared.b32 %0, [%1];" : "=r"(tmem) : "r"(sb));

    loadc(0); loadc(1); loadc(2);

    for (int t = 0; t < NT; t++) {
        if (t <= NT - 3) CP_WAIT2();
        else if (t == NT - 2) CP_WAIT1();
        else CP_WAIT0();
        FENCE_PA();
        __syncthreads();
        if (wid == 0) {
            TCG_FENCE_AFTER();
            if (elect1()) {
                int s = t % 3;
                uint64_t ad = mk_desc(sb + K2_A_OFF + s * 16384);
                uint64_t bd = mk_desc(sb + K2_B_OFF + s * 16384);
#pragma unroll
                for (int k = 0; k < 4; k++)
                    tcg_mma_tf32(tmem, ad + k * 2, bd + k * 2, K2_IDESC, !(t == 0 && k == 0));
                TCG_COMMIT(sb + 8 + (t % 3) * 8);
            }
        }
        int u = t + 3;
        if (u < NT) {
            mb_wait(sb + 8 + (u % 3) * 8, ((u / 3) - 1) & 1);
            loadc(u);
        }
    }
    mb_wait(sb + 8, 1);
    TCG_FENCE_AFTER();

    int rrow = wid * 32 + lane;
    int gr = mBase + rrow;
    int bb = gr / NS;
    int srow = gr - bb * NS;
    float cv = cov[bb * NS + srow];
    const float* decb = g_dec + bb * NH;
    float partial = 0.0f;
#pragma unroll
    for (int blk = 0; blk < 4; blk++) {
        uint32_t d32[32];
        TCG_LD_X32(d32, tmem + blk * 32);
        TCG_WAIT_LD();
#pragma unroll
        for (int j = 0; j < 32; j++) {
            int hc = nBase + blk * 32 + j;
            float x = __uint_as_float(d32[j]) + decb[hc] + cv * Wc[hc];
            partial += av[hc] * tanhf(x);
        }
    }
    atomicAdd(&g_scores[gr], partial);
    TCG_FENCE_BEFORE();
    __syncthreads();
    if (tid == 0) { MB_INVAL(sb + 8); MB_INVAL(sb + 16); MB_INVAL(sb + 24); }
    __syncthreads();
    if (wid == 0) TCG_DEALLOC(tmem, 128);

#else   // ---------------- mma.sync fallback (non-'a' target) ----------------
    __shared__ float ssum[128];
    int g = lane >> 2, tig = lane & 3;
    int warp_m = wid & 1, warp_n = wid >> 1;

    float acc[4][8][4];
#pragma unroll
    for (int i = 0; i < 4; i++)
#pragma unroll
        for (int j = 0; j < 8; j++)
#pragma unroll
            for (int q = 0; q < 4; q++) acc[i][j][q] = 0.0f;

    auto rd = [&](const char* base, int row, int k) -> unsigned {
        uint32_t boff = row * 128 + k * 4;
        uint32_t sw = boff ^ ((boff >> 3) & 0x70);
        return *(const unsigned*)(base + sw);
    };

    loadc(0); loadc(1); loadc(2);
    for (int t = 0; t < NT; t++) {
        if (t <= NT - 3) CP_WAIT2();
        else if (t == NT - 2) CP_WAIT1();
        else CP_WAIT0();
        __syncthreads();
        int s = t % 3;
        const char* ab = smem + K2_A_OFF + s * 16384;
        const char* bbp = smem + K2_B_OFF + s * 16384;
#pragma unroll
        for (int ks = 0; ks < 4; ks++) {
            int kb = ks * 8;
            unsigned bf[8][2];
#pragma unroll
            for (int j = 0; j < 8; j++) {
                int col = warp_n * 64 + j * 8 + g;
                bf[j][0] = rd(bbp, col, kb + tig);
                bf[j][1] = rd(bbp, col, kb + tig + 4);
            }
#pragma unroll
            for (int i = 0; i < 4; i++) {
                int row = warp_m * 64 + i * 16 + g;
                unsigned a0 = rd(ab, row, kb + tig);
                unsigned a1 = rd(ab, row + 8, kb + tig);
                unsigned a2 = rd(ab, row, kb + tig + 4);
                unsigned a3 = rd(ab, row + 8, kb + tig + 4);
#pragma unroll
                for (int j = 0; j < 8; j++)
                    mma_tf32(acc[i][j], a0, a1, a2, a3, bf[j][0], bf[j][1]);
            }
        }
        __syncthreads();
        int u = t + 3;
        if (u < NT) loadc(u);
    }

    ssum[tid] = 0.0f;
    __syncthreads();
#pragma unroll
    for (int i = 0; i < 4; i++) {
#pragma unroll
        for (int h = 0; h < 2; h++) {
            int r = warp_m * 64 + i * 16 + g + h * 8;
            int gr = mBase + r;
            int bb = gr / NS;
            int srow = gr - bb * NS;
            float cv = cov[bb * NS + srow];
            float partial = 0.0f;
#pragma unroll
            for (int j = 0; j < 8; j++) {
                int hc = nBase + warp_n * 64 + j * 8 + 2 * tig;
                float c0 = acc[i][j][h * 2 + 0];
                float c1 = acc[i][j][h * 2 + 1];
                partial += av[hc]     * tanhf(c0 + g_dec[bb * NH + hc]     + cv * Wc[hc]);
                partial += av[hc + 1] * tanhf(c1 + g_dec[bb * NH + hc + 1] + cv * Wc[hc + 1]);
            }
            atomicAdd(&ssum[r], partial);
        }
    }
    __syncthreads();
    atomicAdd(&g_scores[mBase + tid], ssum[tid]);
#endif
}

// ---------------------------------------------------------------------------
// K3: masked softmax, coverage, word_context, p_gen. grid=64, 512 thr.
// ---------------------------------------------------------------------------
__global__ void k3_attn(const float* __restrict__ MB, const float* __restrict__ mask,
                        const float* __restrict__ cov,
                        const int* __restrict__ y, const float* __restrict__ emb_W,
                        const float* __restrict__ pgen_W, const float* __restrict__ pgen_b,
                        float* __restrict__ out, int out_size)
{
    int b = blockIdx.x, tid = threadIdx.x;
    bool full = (out_size >= TOTAL_OUT);
    __shared__ float sc[NS];
    __shared__ float att[NS];
    __shared__ float red[512];
    __shared__ float wcs[NM];

    for (int i = tid; i < NS; i += 512) {
        float m = mask[b * NS + i];
        sc[i] = (m > 0.0f) ? g_scores[b * NS + i] : -1e9f;
    }
    __syncthreads();

    float mx = -1e30f;
    for (int i = tid; i < NS; i += 512) mx = fmaxf(mx, sc[i]);
    red[tid] = mx; __syncthreads();
    for (int o = 256; o > 0; o >>= 1) { if (tid < o) red[tid] = fmaxf(red[tid], red[tid + o]); __syncthreads(); }
    mx = red[0]; __syncthreads();

    float sm = 0.0f;
    for (int i = tid; i < NS; i += 512) { float e = expf(sc[i] - mx); sc[i] = e; sm += e; }
    red[tid] = sm; __syncthreads();
    for (int o = 256; o > 0; o >>= 1) { if (tid < o) red[tid] += red[tid + o]; __syncthreads(); }
    sm = red[0]; __syncthreads();

    float s2 = 0.0f;
    for (int i = tid; i < NS; i += 512) {
        float m = mask[b * NS + i];
        float a = sc[i] / sm * m;
        att[i] = a; s2 += a;
    }
    red[tid] = s2; __syncthreads();
    for (int o = 256; o > 0; o >>= 1) { if (tid < o) red[tid] += red[tid + o]; __syncthreads(); }
    s2 = red[0]; __syncthreads();
    float inv = 1.0f / (s2 + 1e-10f);
    for (int i = tid; i < NS; i += 512) {
        float a = att[i] * inv;
        att[i] = a;
        g_attn[b * NS + i] = a;
        if (full) {
            out[OFF_AT + b * NS + i] = a;
            out[OFF_CV + b * NS + i] = cov[b * NS + i] + a;
        }
    }
    __syncthreads();

    {
        float a0 = 0.f, a1 = 0.f, a2 = 0.f, a3 = 0.f;
        const float* mbb = MB + (size_t)b * NS * NM + tid;
#pragma unroll 4
        for (int s = 0; s < NS; s += 4) {
            a0 += att[s]     * mbb[(size_t)s * NM];
            a1 += att[s + 1] * mbb[(size_t)(s + 1) * NM];
            a2 += att[s + 2] * mbb[(size_t)(s + 2) * NM];
            a3 += att[s + 3] * mbb[(size_t)(s + 3) * NM];
        }
        float a = (a0 + a1) + (a2 + a3);
        wcs[tid] = a;
        g_cat[b * (NM + NH) + tid] = a;
        if (full) out[OFF_WC + b * NM + tid] = a;
    }
    __syncthreads();

    int yb = y[b];
    float ps = 0.0f;
    for (int i = tid; i < NM + NH + NE; i += 512) {
        float xv = (i < NM) ? wcs[i]
                 : (i < NM + NH) ? g_h1[b * NH + (i - NM)]
                 : emb_W[(size_t)yb * NE + (i - NM - NH)];
        ps += pgen_W[i] * xv;
    }
    red[tid] = ps; __syncthreads();
    for (int o = 256; o > 0; o >>= 1) { if (tid < o) red[tid] += red[tid + o]; __syncthreads(); }
    if (tid == 0) {
        float p = sigmoidf_(red[0] + pgen_b[0]);
        g_pgen[b] = p;
        if (full) out[OFF_PG + b] = p;
    }
}

// ---------------------------------------------------------------------------
// K4a: vocab logits on tcgen05. D[128 vocab, 128 pad-b] = W2tile @ hidp^T.
// Epilogue: smem tile + simple column sums; g_logits in [b][v] layout.
// (validated round 13)
// ---------------------------------------------------------------------------
#define K4_A_OFF 1024
#define K4_B_OFF (1024 + 3 * 16384)
#define K4_SMEM  (1024 + 6 * 16384)   // 99328
#define ES_LD 65

__global__ __launch_bounds__(128, 1)
void k4a_tc(const float* __restrict__ W2, const float* __restrict__ b2)
{
    extern __shared__ char smem[];
    int tid = threadIdx.x, wid = tid >> 5;
    int vBase = blockIdx.x * 128;
    const int NT = NH / 32;   // 16 chunks

    auto loadc = [&](int u) {
        int s = u % 3;
        int k0 = u * 32;
        char* abase = smem + K4_A_OFF + s * 16384;
        char* bbase = smem + K4_B_OFF + s * 16384;
#pragma unroll
        for (int i = 0; i < 8; i++) {
            int idx = tid + i * 128;
            int row = idx >> 3, c = idx & 7;
            uint32_t boff = row * 128 + c * 16;
            uint32_t sw = boff ^ ((boff >> 3) & 0x70);
            int vr = vBase + row;
            cpa16p((float*)(abase + sw), &W2[(size_t)vr * NH + k0 + c * 4], vr < NV);
        }
#pragma unroll
        for (int i = 0; i < 8; i++) {
            int idx = tid + i * 128;
            int row = idx >> 3, c = idx & 7;
            uint32_t boff = row * 128 + c * 16;
            uint32_t sw = boff ^ ((boff >> 3) & 0x70);
            cpa16((float*)(bbase + sw), &g_hidp[(size_t)row * NH + k0 + c * 4]);
        }
        CP_COMMIT();
    };

#if USE_TCGEN05
    uint32_t sb = smem_u32(smem);
    if (wid == 0) { TCG_ALLOC(sb, 128); TCG_RELQ(); }
    if (tid == 0) { MB_INIT(sb + 8, 1); MB_INIT(sb + 16, 1); MB_INIT(sb + 24, 1); }
    __syncthreads();
    uint32_t tmem;
    asm volatile("ld.shared.b32 %0, [%1];" : "=r"(tmem) : "r"(sb));

    loadc(0); loadc(1); loadc(2);

    for (int t = 0; t < NT; t++) {
        if (t <= NT - 3) CP_WAIT2();
        else if (t == NT - 2) CP_WAIT1();
        else CP_WAIT0();
        FENCE_PA();
        __syncthreads();
        if (wid == 0) {
            TCG_FENCE_AFTER();
            if (elect1()) {
                int s = t % 3;
                uint64_t ad = mk_desc(sb + K4_A_OFF + s * 16384);
                uint64_t bd = mk_desc(sb + K4_B_OFF + s * 16384);
#pragma unroll
                for (int k = 0; k < 4; k++)
                    tcg_mma_tf32(tmem, ad + k * 2, bd + k * 2, K2_IDESC, !(t == 0 && k == 0));
                TCG_COMMIT(sb + 8 + (t % 3) * 8);
            }
        }
        int u = t + 3;
        if (u < NT) {
            mb_wait(sb + 8 + (u % 3) * 8, ((u / 3) - 1) & 1);
            loadc(u);
        }
    }
    mb_wait(sb + 8, 1);
    TCG_FENCE_AFTER();
    __syncthreads();

    float* es = (float*)(smem + K4_A_OFF);
    int v = vBase + tid;
    bool valid = (v < NV);
    float bias = valid ? b2[v] : 0.0f;
    {
        uint32_t d0[32];
        TCG_LD_X32(d0, tmem);
        TCG_WAIT_LD();
#pragma unroll
        for (int j = 0; j < 32; j++)
            es[tid * ES_LD + j] = valid ? expf(__uint_as_float(d0[j]) + bias) : 0.0f;
    }
    {
        uint32_t d1[32];
        TCG_LD_X32(d1, tmem + 32);
        TCG_WAIT_LD();
#pragma unroll
        for (int j = 0; j < 32; j++)
            es[tid * ES_LD + 32 + j] = valid ? expf(__uint_as_float(d1[j]) + bias) : 0.0f;
    }
    TCG_FENCE_BEFORE();
    __syncthreads();

    if (tid < 64) {
        float s = 0.0f;
#pragma unroll 8
        for (int r = 0; r < 128; r++) s += es[r * ES_LD + tid];
        atomicAdd(&g_sumexp[tid], s);
    }
    if (valid) {
#pragma unroll 4
        for (int b = 0; b < NB; b++)
            g_logits[(size_t)b * NV + v] = es[tid * ES_LD + b];
    }
    __syncthreads();
    if (tid == 0) { MB_INVAL(sb + 8); MB_INVAL(sb + 16); MB_INVAL(sb + 24); }
    __syncthreads();
    if (wid == 0) TCG_DEALLOC(tmem, 128);

#else   // scalar fallback
    int v = vBase + tid;
    if (v < NV) {
        float bias = b2[v];
        float s[NB];
        for (int b = 0; b < NB; b++) {
            float acc = bias;
            for (int k = 0; k < NH; k++)
                acc += W2[(size_t)v * NH + k] * g_hidp[(size_t)b * NH + k];
            s[b] = expf(acc);
            g_logits[(size_t)b * NV + v] = s[b];
        }
        for (int b = 0; b < NB; b++) atomicAdd(&g_sumexp[b], s[b]);
    }
#endif
}

// ---------------------------------------------------------------------------
// K4b: normalize + write final vocab part. grid=(64, 8), 256 thr. float4.
// ---------------------------------------------------------------------------
#define VCHUNK 6250
__global__ void k4b_norm(float* __restrict__ out)
{
    int b = blockIdx.x, ch = blockIdx.y, tid = threadIdx.x;
    float scale = g_pgen[b] / g_sumexp[b];
    const float* lg = &g_logits[(size_t)b * NV];
    float* orow = out + (size_t)b * NVO;
    int v0 = ch * VCHUNK;
    // VCHUNK=6250: 1562 float4 groups + 2 tail floats; v0 is 2-aligned only,
    // so use float2 base with stride-1024 float4 when aligned:
    for (int v = v0 + tid * 4; v + 3 < v0 + VCHUNK; v += 1024) {
        if ((v & 3) == 0) {
            float4 e = *(const float4*)&lg[v];
            e.x *= scale; e.y *= scale; e.z *= scale; e.w *= scale;
            *(float4*)&orow[v] = e;
        } else {
            orow[v] = lg[v] * scale; orow[v + 1] = lg[v + 1] * scale;
            orow[v + 2] = lg[v + 2] * scale; orow[v + 3] = lg[v + 3] * scale;
        }
    }
    // tail (last <4 elements of the chunk)
    int tail = v0 + ((VCHUNK / 4) * 4);
    for (int v = tail + tid; v < v0 + VCHUNK; v += 256) orow[v] = lg[v] * scale;
    if (ch == 0) {
        for (int v = NV + tid; v < NVO; v += 256) orow[v] = 0.0f;
    }
}

// ---------------------------------------------------------------------------
// K4c: OOV pointer scatter. grid=64, 400 thr.
// ---------------------------------------------------------------------------
__global__ void k4c_scatter(const int* __restrict__ src_oov, float* __restrict__ out)
{
    int b = blockIdx.x, s = threadIdx.x;
    float q = 1.0f - g_pgen[b];
    float* orow = out + (size_t)b * NVO;
    atomicAdd(&orow[src_oov[b * NS + s]], q * g_attn[b * NS + s]);
}

// ---------------------------------------------------------------------------
extern "C" void kernel_launch(void* const* d_in, const int* in_sizes, int n_in,
                              void* d_out, int out_size)
{
    int sh = (n_in >= 23) ? 1 : 0;
    const int*   y        = (const int*)  d_in[0];
    const float* h0g      = (const float*)d_in[1];
    const float* MB       = (const float*)d_in[2];
    const float* mask     = (const float*)d_in[3];
    const int*   src_oov  = (const int*)  d_in[4 + sh];
    const float* cov      = (const float*)d_in[5 + sh];
    const float* emb_W    = (const float*)d_in[6 + sh];
    const float* Wih      = (const float*)d_in[7 + sh];
    const float* Whh      = (const float*)d_in[8 + sh];
    const float* bih      = (const float*)d_in[9 + sh];
    const float* bhh      = (const float*)d_in[10 + sh];
    const float* Wm       = (const float*)d_in[11 + sh];
    const float* Wd       = (const float*)d_in[12 + sh];
    const float* bd       = (const float*)d_in[13 + sh];
    const float* Wc       = (const float*)d_in[14 + sh];
    const float* av       = (const float*)d_in[15 + sh];
    const float* pgen_W   = (const float*)d_in[16 + sh];
    const float* pgen_b   = (const float*)d_in[17 + sh];
    const float* vd1_W    = (const float*)d_in[18 + sh];
    const float* vd1_b    = (const float*)d_in[19 + sh];
    const float* W2       = (const float*)d_in[20 + sh];
    const float* b2       = (const float*)d_in[21 + sh];
    float* out = (float*)d_out;

    float *p_emb, *p_gi, *p_gh, *p_h1, *p_dec, *p_cat, *p_hidp;
    cudaGetSymbolAddress((void**)&p_emb,  g_emb);
    cudaGetSymbolAddress((void**)&p_gi,   g_gi);
    cudaGetSymbolAddress((void**)&p_gh,   g_gh);
    cudaGetSymbolAddress((void**)&p_h1,   g_h1);
    cudaGetSymbolAddress((void**)&p_dec,  g_dec);
    cudaGetSymbolAddress((void**)&p_cat,  g_cat);
    cudaGetSymbolAddress((void**)&p_hidp, g_hidp);

    cudaFuncSetAttribute(k2_tc,  cudaFuncAttributeMaxDynamicSharedMemorySize, K2_SMEM);
    cudaFuncSetAttribute(k4a_tc, cudaFuncAttributeMaxDynamicSharedMemorySize, K4_SMEM);

    k0_init<<<NB, 256>>>(y, emb_W);

    gemm_nt<128><<<3 * NH / 64, 256>>>(p_emb, Wih, bih, p_gi, 3 * NH);   // gi
    gemm_nt<512><<<3 * NH / 64, 256>>>(h0g,   Whh, bhh, p_gh, 3 * NH);   // gh
    k1b_combine<<<NB, 512>>>(h0g, out, out_size);
    gemm_nt<512><<<NH / 64, 256>>>(p_h1, Wd, bd, p_dec, NH);             // dec_feat

    dim3 g2(NM / 128, (NB * NS) / 128);   // (4, 200)
    k2_tc<<<g2, 128, K2_SMEM>>>(MB, Wm, Wc, av, cov);

    k3_attn<<<NB, 512>>>(MB, mask, cov, y, emb_W, pgen_W, pgen_b, out, out_size);

    gemm_nt<1024><<<NH / 64, 256>>>(p_cat, vd1_W, vd1_b, p_hidp, NH);    // vd1

    k4a_tc<<<(NV + 127) / 128, 128, K4_SMEM>>>(W2, b2);

    dim3 g4b(NB, 8);
    k4b_norm<<<g4b, 256>>>(out);
    k4c_scatter<<<NB, NS>>>(src_oov, out);
}

// round 17
// speedup vs baseline: 1.5690x; 1.0391x over previous
#include <cuda_runtime.h>
#include <math.h>
#include <stdint.h>

// Problem constants
#define NB 64
#define NS 400
#define NV 50000
#define NE 128
#define NH 512
#define NM 512
#define NOOV 20
#define NVO (NV + NOOV)

// Output layout (flattened concatenation of reference outputs)
#define SZ_FD   (NB * NVO)
#define OFF_H   (SZ_FD)
#define OFF_WC  (OFF_H  + NB * NH)
#define OFF_AT  (OFF_WC + NB * NM)
#define OFF_PG  (OFF_AT + NB * NS)
#define OFF_CV  (OFF_PG + NB)
#define TOTAL_OUT (OFF_CV + NB * NS)

// tcgen05 only exists on the 'a' feature targets; the harness also builds a
// plain compute_103 PTX pass which must not see those instructions.
#if !defined(__CUDA_ARCH__) || defined(__CUDA_ARCH_FEAT_SM103_ALL) || defined(__CUDA_ARCH_FEAT_SM100_ALL) || defined(__CUDA_ARCH_FEAT_SM101_ALL)
#define USE_TCGEN05 1
#else
#define USE_TCGEN05 0
#endif

// Scratch (device globals)
__device__ float g_gi[NB * 3 * NH];
__device__ float g_gh[NB * 3 * NH];
__device__ float g_h1[NB * NH];
__device__ float g_dec[NB * NH];
__device__ float g_scores[NB * NS];
__device__ float g_attn[NB * NS];
__device__ float g_cat[NB * (NM + NH)];   // [wc | h1]
__device__ float g_hidp[128 * NH];        // rows 64..127 never written: zero-init
__device__ float g_pgen[NB];
__device__ float g_sumexp[NB];
__device__ float g_logits[(size_t)NB * NV];   // exp(logit), [b][v]

__device__ __forceinline__ float sigmoidf_(float x) { return 1.0f / (1.0f + expf(-x)); }

// tf32 mma.sync fed raw fp32 bits (HW truncates mantissa to tf32).
__device__ __forceinline__ void mma_tf32(float c[4], unsigned a0, unsigned a1,
                                         unsigned a2, unsigned a3,
                                         unsigned b0, unsigned b1) {
    asm volatile("mma.sync.aligned.m16n8k8.row.col.f32.tf32.tf32.f32 "
                 "{%0,%1,%2,%3}, {%4,%5,%6,%7}, {%8,%9}, {%0,%1,%2,%3};"
                 : "+f"(c[0]), "+f"(c[1]), "+f"(c[2]), "+f"(c[3])
                 : "r"(a0), "r"(a1), "r"(a2), "r"(a3), "r"(b0), "r"(b1));
}
__device__ __forceinline__ void cpa16(float* s, const float* g) {
    unsigned sa = (unsigned)__cvta_generic_to_shared(s);
    asm volatile("cp.async.cg.shared.global [%0], [%1], 16;" :: "r"(sa), "l"(g));
}
__device__ __forceinline__ void cpa16p(float* s, const float* g, bool ok) {
    unsigned sa = (unsigned)__cvta_generic_to_shared(s);
    int sz = ok ? 16 : 0;
    asm volatile("cp.async.cg.shared.global [%0], [%1], 16, %2;" :: "r"(sa), "l"(g), "r"(sz));
}
#define CP_COMMIT() asm volatile("cp.async.commit_group;")
#define CP_WAIT2()  asm volatile("cp.async.wait_group 2;")
#define CP_WAIT1()  asm volatile("cp.async.wait_group 1;")
#define CP_WAIT0()  asm volatile("cp.async.wait_group 0;")

__device__ __forceinline__ unsigned ldb(const float* p) {
    return __float_as_uint(*p);
}

// ---------------- tcgen05 helpers (sm_103a only) ----------------
__device__ __forceinline__ uint32_t smem_u32(const void* p) {
    uint32_t a;
    asm("{ .reg .u64 t; cvta.to.shared.u64 t, %1; cvt.u32.u64 %0, t; }" : "=r"(a) : "l"(p));
    return a;
}
__device__ __forceinline__ uint32_t elect1() {
    uint32_t p;
    asm volatile("{\n\t.reg .pred p;\n\telect.sync _|p, 0xFFFFFFFF;\n\tselp.b32 %0,1,0,p;\n\t}" : "=r"(p));
    return p;
}
#define MB_INIT(a,c) asm volatile("mbarrier.init.shared.b64 [%0], %1;" :: "r"(a), "r"(c) : "memory")
#define MB_INVAL(a)  asm volatile("mbarrier.inval.shared.b64 [%0];" :: "r"(a) : "memory")
__device__ __forceinline__ void mb_wait(uint32_t addr, uint32_t parity) {
    uint32_t done;
    asm volatile("{\n\t.reg .pred p;\n\t"
                 "mbarrier.try_wait.parity.acquire.cta.shared::cta.b64 p, [%1], %2;\n\t"
                 "selp.b32 %0,1,0,p;\n\t}" : "=r"(done) : "r"(addr), "r"(parity) : "memory");
    while (!done) {
        asm volatile("{\n\t.reg .pred p;\n\t"
                     "mbarrier.try_wait.parity.acquire.cta.shared::cta.b64 p, [%1], %2, 0x989680;\n\t"
                     "selp.b32 %0,1,0,p;\n\t}" : "=r"(done) : "r"(addr), "r"(parity) : "memory");
    }
}
#define TCG_ALLOC(sa,n)  asm volatile("tcgen05.alloc.cta_group::1.sync.aligned.shared::cta.b32 [%0], %1;" :: "r"(sa), "r"(n) : "memory")
#define TCG_RELQ()       asm volatile("tcgen05.relinquish_alloc_permit.cta_group::1.sync.aligned;")
#define TCG_DEALLOC(t,n) asm volatile("tcgen05.dealloc.cta_group::1.sync.aligned.b32 %0, %1;" :: "r"(t), "r"(n))
#define TCG_COMMIT(a)    asm volatile("tcgen05.commit.cta_group::1.mbarrier::arrive::one.shared::cluster.b64 [%0];" :: "r"(a) : "memory")
#define TCG_FENCE_AFTER()  asm volatile("tcgen05.fence::after_thread_sync;" ::: "memory")
#define TCG_FENCE_BEFORE() asm volatile("tcgen05.fence::before_thread_sync;" ::: "memory")
#define TCG_WAIT_LD()    asm volatile("tcgen05.wait::ld.sync.aligned;" ::: "memory")
#define FENCE_PA()       asm volatile("fence.proxy.async.shared::cta;" ::: "memory")

#define TCG_LD_X32(r, tmem_addr) \
    asm volatile( \
        "tcgen05.ld.sync.aligned.32x32b.x32.b32 " \
        "{%0, %1, %2, %3, %4, %5, %6, %7, " \
        " %8, %9, %10, %11, %12, %13, %14, %15, " \
        " %16, %17, %18, %19, %20, %21, %22, %23, " \
        " %24, %25, %26, %27, %28, %29, %30, %31}, [%32];" \
        : "=r"((r)[0]),  "=r"((r)[1]),  "=r"((r)[2]),  "=r"((r)[3]), \
          "=r"((r)[4]),  "=r"((r)[5]),  "=r"((r)[6]),  "=r"((r)[7]), \
          "=r"((r)[8]),  "=r"((r)[9]),  "=r"((r)[10]), "=r"((r)[11]), \
          "=r"((r)[12]), "=r"((r)[13]), "=r"((r)[14]), "=r"((r)[15]), \
          "=r"((r)[16]), "=r"((r)[17]), "=r"((r)[18]), "=r"((r)[19]), \
          "=r"((r)[20]), "=r"((r)[21]), "=r"((r)[22]), "=r"((r)[23]), \
          "=r"((r)[24]), "=r"((r)[25]), "=r"((r)[26]), "=r"((r)[27]), \
          "=r"((r)[28]), "=r"((r)[29]), "=r"((r)[30]), "=r"((r)[31]) \
        : "r"(tmem_addr))

// SW128 K-major smem descriptor (layout=2, version=1, SBO=64, LBO=1)
__device__ __forceinline__ uint64_t mk_desc(uint32_t addr) {
    return ((uint64_t)2 << 61) | ((uint64_t)1 << 46) | ((uint64_t)64 << 32)
         | ((uint64_t)1 << 16) | ((uint64_t)(addr >> 4) & 0x3FFF);
}

// idesc: c=F32(1<<4), a=TF32(2<<7), b=TF32(2<<10), N=128 (16<<17), M=128 (8<<24)
#define K2_IDESC ((1u << 4) | (2u << 7) | (2u << 10) | (16u << 17) | (8u << 24))

#if USE_TCGEN05
__device__ __forceinline__ void tcg_mma_tf32(uint32_t d, uint64_t ad, uint64_t bd,
                                             uint32_t id, bool en) {
    uint32_t e = en ? 1u : 0u, z = 0u;
    asm volatile("{\n\t.reg .pred p;\n\tsetp.ne.u32 p, %5, 0;\n\t"
                 "tcgen05.mma.cta_group::1.kind::tf32 [%0], %1, %2, %3, {%4,%4,%4,%4}, p;\n\t}"
                 :: "r"(d), "l"(ad), "l"(bd), "r"(id), "r"(z), "r"(e) : "memory");
}
#endif

#define GLD 36

// ---------------------------------------------------------------------------
// Shared GEMM body (dynamic smem): C[64, N] = X[64, K] @ W[N, K]^T + bias.
// GATHER: X row r = emb_W[y[r]] (K==NE). Dynamic smem: 4 * 64*GLD floats.
// ---------------------------------------------------------------------------
template<int K, bool GATHER>
__device__ __forceinline__ void gemm_body(const int* __restrict__ y,
                                          const float* __restrict__ X,
                                          const float* __restrict__ W,
                                          const float* __restrict__ bias,
                                          float* __restrict__ C, int N, int nBase)
{
    extern __shared__ float dyn[];
    float* Xs[2] = { dyn,                dyn + 64 * GLD };
    float* Ws[2] = { dyn + 2 * 64 * GLD, dyn + 3 * 64 * GLD };
    __shared__ int ys[64];

    int tid = threadIdx.x, wid = tid >> 5, lane = tid & 31;
    int g = lane >> 2, tig = lane & 3;
    int warp_m = wid & 1, warp_n = wid >> 1;

    if (GATHER) {
        if (tid < 64) ys[tid] = y[tid];
        __syncthreads();
    }

    float acc[2][2][4];
#pragma unroll
    for (int i = 0; i < 2; i++)
#pragma unroll
        for (int j = 0; j < 2; j++)
#pragma unroll
            for (int q = 0; q < 4; q++) acc[i][j][q] = 0.0f;

    auto load = [&](int s, int k0) {
#pragma unroll
        for (int it = 0; it < 2; it++) {
            int c = tid + it * 256;
            int row = c >> 3, c4 = (c & 7) * 4;
            const float* xsrc = GATHER
                ? &X[(size_t)ys[row] * K + k0 + c4]
                : &X[(size_t)row * K + k0 + c4];
            cpa16(&Xs[s][row * GLD + c4], xsrc);
            cpa16(&Ws[s][row * GLD + c4], &W[(size_t)(nBase + row) * K + k0 + c4]);
        }
    };

    const int NT = K / 32;
    load(0, 0); CP_COMMIT();
    for (int t = 0; t < NT; t++) {
        if (t + 1 < NT) { load((t + 1) & 1, (t + 1) * 32); CP_COMMIT(); CP_WAIT1(); }
        else CP_WAIT0();
        __syncthreads();
        int s = t & 1;
#pragma unroll
        for (int ks = 0; ks < 4; ks++) {
            int kb = ks * 8;
            unsigned bf[2][2];
#pragma unroll
            for (int j = 0; j < 2; j++) {
                int col = warp_n * 16 + j * 8 + g;
                bf[j][0] = ldb(&Ws[s][col * GLD + kb + tig]);
                bf[j][1] = ldb(&Ws[s][col * GLD + kb + tig + 4]);
            }
#pragma unroll
            for (int i = 0; i < 2; i++) {
                int row = warp_m * 32 + i * 16 + g;
                unsigned a0 = ldb(&Xs[s][row * GLD + kb + tig]);
                unsigned a1 = ldb(&Xs[s][(row + 8) * GLD + kb + tig]);
                unsigned a2 = ldb(&Xs[s][row * GLD + kb + tig + 4]);
                unsigned a3 = ldb(&Xs[s][(row + 8) * GLD + kb + tig + 4]);
#pragma unroll
                for (int j = 0; j < 2; j++)
                    mma_tf32(acc[i][j], a0, a1, a2, a3, bf[j][0], bf[j][1]);
            }
        }
        __syncthreads();
    }

#pragma unroll
    for (int i = 0; i < 2; i++) {
        int bb = warp_m * 32 + i * 16 + g;
#pragma unroll
        for (int j = 0; j < 2; j++) {
            int v = nBase + warp_n * 16 + j * 8 + 2 * tig;
            C[(size_t)bb * N + v]           = acc[i][j][0] + bias[v];
            C[(size_t)bb * N + v + 1]       = acc[i][j][1] + bias[v + 1];
            C[(size_t)(bb + 8) * N + v]     = acc[i][j][2] + bias[v];
            C[(size_t)(bb + 8) * N + v + 1] = acc[i][j][3] + bias[v + 1];
        }
    }
}

#define GEMM_DYN_SMEM (4 * 64 * GLD * 4)   // 36864 bytes

// ---------------------------------------------------------------------------
// K1a: fused GRU input GEMMs. Blocks 0..23: gi = emb[y] @ Wih^T (K=128);
// blocks 24..47: gh = h0 @ Whh^T (K=512). Runs both concurrently.
// ---------------------------------------------------------------------------
__global__ __launch_bounds__(256, 1)
void k1a_gru_gemms(const int* __restrict__ y, const float* __restrict__ emb_W,
                   const float* __restrict__ h0g,
                   const float* __restrict__ Wih, const float* __restrict__ bih,
                   const float* __restrict__ Whh, const float* __restrict__ bhh)
{
    if (blockIdx.x < 24)
        gemm_body<NE, true>(y, emb_W, Wih, bih, g_gi, 3 * NH, blockIdx.x * 64);
    else
        gemm_body<NH, false>(nullptr, h0g, Whh, bhh, g_gh, 3 * NH,
                             (blockIdx.x - 24) * 64);
}

// ---------------------------------------------------------------------------
// Generic small GEMM kernel (dec, vd1): static smem variant.
// ---------------------------------------------------------------------------
template<int K>
__global__ __launch_bounds__(256, 1)
void gemm_nt(const float* __restrict__ X, const float* __restrict__ W,
             const float* __restrict__ bias, float* __restrict__ C, int N)
{
    gemm_body<K, false>(nullptr, X, W, bias, C, N, blockIdx.x * 64);
}

// ---------------------------------------------------------------------------
// K1b: GRU gate combine + scratch zeroing. grid=64, 512 thr.
// ---------------------------------------------------------------------------
__global__ void k1b_combine(const float* __restrict__ h0g, float* __restrict__ out,
                            int out_size)
{
    int b = blockIdx.x, j = threadIdx.x;
    float gir = g_gi[b * 3 * NH + j];
    float giz = g_gi[b * 3 * NH + NH + j];
    float gin = g_gi[b * 3 * NH + 2 * NH + j];
    float ghr = g_gh[b * 3 * NH + j];
    float ghz = g_gh[b * 3 * NH + NH + j];
    float ghn = g_gh[b * 3 * NH + 2 * NH + j];
    float h0 = h0g[b * NH + j];
    float r = sigmoidf_(gir + ghr);
    float z = sigmoidf_(giz + ghz);
    float n = tanhf(gin + r * ghn);
    float hv = (1.0f - z) * n + z * h0;
    g_h1[b * NH + j] = hv;
    g_cat[b * (NM + NH) + NM + j] = hv;
    if (out_size >= TOTAL_OUT) out[OFF_H + b * NH + j] = hv;
    // zero per-replay scratch (k2 atomics, k4a sums)
    for (int i = j; i < NS; i += 512) g_scores[b * NS + i] = 0.0f;
    if (b == 0 && j < NB) g_sumexp[j] = 0.0f;
}

// ---------------------------------------------------------------------------
// K2: enc_feat GEMM + fused score epilogue. 128x128x512 per CTA, 128 thr.
// grid (4 n-blocks, 200 m-blocks). tcgen05 tf32 SS path (round-13 proven).
// ---------------------------------------------------------------------------
#define K2_A_OFF 1024
#define K2_B_OFF (1024 + 3 * 16384)
#define K2_SMEM  (1024 + 6 * 16384)   // 99328

__global__ __launch_bounds__(128, 1)
void k2_tc(const float* __restrict__ MB, const float* __restrict__ Wm,
           const float* __restrict__ Wc, const float* __restrict__ av,
           const float* __restrict__ cov)
{
    extern __shared__ char smem[];
    int tid = threadIdx.x, wid = tid >> 5, lane = tid & 31;
    int mBase = blockIdx.y * 128, nBase = blockIdx.x * 128;
    const int NT = NM / 32;   // 16 chunks

    auto loadc = [&](int u) {
        int s = u % 3;
        int k0 = u * 32;
        char* abase = smem + K2_A_OFF + s * 16384;
        char* bbase = smem + K2_B_OFF + s * 16384;
#pragma unroll
        for (int i = 0; i < 8; i++) {
            int idx = tid + i * 128;
            int row = idx >> 3, c = idx & 7;
            uint32_t boff = row * 128 + c * 16;
            uint32_t sw = boff ^ ((boff >> 3) & 0x70);
            cpa16((float*)(abase + sw), &MB[(size_t)(mBase + row) * NM + k0 + c * 4]);
            cpa16((float*)(bbase + sw), &Wm[(size_t)(nBase + row) * NM + k0 + c * 4]);
        }
        CP_COMMIT();
    };

#if USE_TCGEN05
    uint32_t sb = smem_u32(smem);
    if (wid == 0) { TCG_ALLOC(sb, 128); TCG_RELQ(); }
    if (tid == 0) { MB_INIT(sb + 8, 1); MB_INIT(sb + 16, 1); MB_INIT(sb + 24, 1); }
    __syncthreads();
    uint32_t tmem;
    asm volatile("ld.shared.b32 %0, [%1];" : "=r"(tmem) : "r"(sb));

    loadc(0); loadc(1); loadc(2);

    for (int t = 0; t < NT; t++) {
        if (t <= NT - 3) CP_WAIT2();
        else if (t == NT - 2) CP_WAIT1();
        else CP_WAIT0();
        FENCE_PA();
        __syncthreads();
        if (wid == 0) {
            TCG_FENCE_AFTER();
            if (elect1()) {
                int s = t % 3;
                uint64_t ad = mk_desc(sb + K2_A_OFF + s * 16384);
                uint64_t bd = mk_desc(sb + K2_B_OFF + s * 16384);
#pragma unroll
                for (int k = 0; k < 4; k++)
                    tcg_mma_tf32(tmem, ad + k * 2, bd + k * 2, K2_IDESC, !(t == 0 && k == 0));
                TCG_COMMIT(sb + 8 + (t % 3) * 8);
            }
        }
        int u = t + 3;
        if (u < NT) {
            mb_wait(sb + 8 + (u % 3) * 8, ((u / 3) - 1) & 1);
            loadc(u);
        }
    }
    mb_wait(sb + 8, 1);
    TCG_FENCE_AFTER();

    int rrow = wid * 32 + lane;
    int gr = mBase + rrow;
    int bb = gr / NS;
    int srow = gr - bb * NS;
    float cv = cov[bb * NS + srow];
    const float* decb = g_dec + bb * NH;
    float partial = 0.0f;
#pragma unroll
    for (int blk = 0; blk < 4; blk++) {
        uint32_t d32[32];
        TCG_LD_X32(d32, tmem + blk * 32);
        TCG_WAIT_LD();
#pragma unroll
        for (int j = 0; j < 32; j++) {
            int hc = nBase + blk * 32 + j;
            float x = __uint_as_float(d32[j]) + decb[hc] + cv * Wc[hc];
            partial += av[hc] * tanhf(x);
        }
    }
    atomicAdd(&g_scores[gr], partial);
    TCG_FENCE_BEFORE();
    __syncthreads();
    if (tid == 0) { MB_INVAL(sb + 8); MB_INVAL(sb + 16); MB_INVAL(sb + 24); }
    __syncthreads();
    if (wid == 0) TCG_DEALLOC(tmem, 128);

#else   // ---------------- mma.sync fallback (non-'a' target) ----------------
    __shared__ float ssum[128];
    int g = lane >> 2, tig = lane & 3;
    int warp_m = wid & 1, warp_n = wid >> 1;

    float acc[4][8][4];
#pragma unroll
    for (int i = 0; i < 4; i++)
#pragma unroll
        for (int j = 0; j < 8; j++)
#pragma unroll
            for (int q = 0; q < 4; q++) acc[i][j][q] = 0.0f;

    auto rd = [&](const char* base, int row, int k) -> unsigned {
        uint32_t boff = row * 128 + k * 4;
        uint32_t sw = boff ^ ((boff >> 3) & 0x70);
        return *(const unsigned*)(base + sw);
    };

    loadc(0); loadc(1); loadc(2);
    for (int t = 0; t < NT; t++) {
        if (t <= NT - 3) CP_WAIT2();
        else if (t == NT - 2) CP_WAIT1();
        else CP_WAIT0();
        __syncthreads();
        int s = t % 3;
        const char* ab = smem + K2_A_OFF + s * 16384;
        const char* bbp = smem + K2_B_OFF + s * 16384;
#pragma unroll
        for (int ks = 0; ks < 4; ks++) {
            int kb = ks * 8;
            unsigned bf[8][2];
#pragma unroll
            for (int j = 0; j < 8; j++) {
                int col = warp_n * 64 + j * 8 + g;
                bf[j][0] = rd(bbp, col, kb + tig);
                bf[j][1] = rd(bbp, col, kb + tig + 4);
            }
#pragma unroll
            for (int i = 0; i < 4; i++) {
                int row = warp_m * 64 + i * 16 + g;
                unsigned a0 = rd(ab, row, kb + tig);
                unsigned a1 = rd(ab, row + 8, kb + tig);
                unsigned a2 = rd(ab, row, kb + tig + 4);
                unsigned a3 = rd(ab, row + 8, kb + tig + 4);
#pragma unroll
                for (int j = 0; j < 8; j++)
                    mma_tf32(acc[i][j], a0, a1, a2, a3, bf[j][0], bf[j][1]);
            }
        }
        __syncthreads();
        int u = t + 3;
        if (u < NT) loadc(u);
    }

    ssum[tid] = 0.0f;
    __syncthreads();
#pragma unroll
    for (int i = 0; i < 4; i++) {
#pragma unroll
        for (int h = 0; h < 2; h++) {
            int r = warp_m * 64 + i * 16 + g + h * 8;
            int gr = mBase + r;
            int bb = gr / NS;
            int srow = gr - bb * NS;
            float cv = cov[bb * NS + srow];
            float partial = 0.0f;
#pragma unroll
            for (int j = 0; j < 8; j++) {
                int hc = nBase + warp_n * 64 + j * 8 + 2 * tig;
                float c0 = acc[i][j][h * 2 + 0];
                float c1 = acc[i][j][h * 2 + 1];
                partial += av[hc]     * tanhf(c0 + g_dec[bb * NH + hc]     + cv * Wc[hc]);
                partial += av[hc + 1] * tanhf(c1 + g_dec[bb * NH + hc + 1] + cv * Wc[hc + 1]);
            }
            atomicAdd(&ssum[r], partial);
        }
    }
    __syncthreads();
    atomicAdd(&g_scores[mBase + tid], ssum[tid]);
#endif
}

// ---------------------------------------------------------------------------
// K3: masked softmax, coverage, word_context, p_gen. grid=64, 512 thr.
// ---------------------------------------------------------------------------
__global__ void k3_attn(const float* __restrict__ MB, const float* __restrict__ mask,
                        const float* __restrict__ cov,
                        const int* __restrict__ y, const float* __restrict__ emb_W,
                        const float* __restrict__ pgen_W, const float* __restrict__ pgen_b,
                        float* __restrict__ out, int out_size)
{
    int b = blockIdx.x, tid = threadIdx.x;
    bool full = (out_size >= TOTAL_OUT);
    __shared__ float sc[NS];
    __shared__ float att[NS];
    __shared__ float red[512];
    __shared__ float wcs[NM];

    for (int i = tid; i < NS; i += 512) {
        float m = mask[b * NS + i];
        sc[i] = (m > 0.0f) ? g_scores[b * NS + i] : -1e9f;
    }
    __syncthreads();

    float mx = -1e30f;
    for (int i = tid; i < NS; i += 512) mx = fmaxf(mx, sc[i]);
    red[tid] = mx; __syncthreads();
    for (int o = 256; o > 0; o >>= 1) { if (tid < o) red[tid] = fmaxf(red[tid], red[tid + o]); __syncthreads(); }
    mx = red[0]; __syncthreads();

    float sm = 0.0f;
    for (int i = tid; i < NS; i += 512) { float e = expf(sc[i] - mx); sc[i] = e; sm += e; }
    red[tid] = sm; __syncthreads();
    for (int o = 256; o > 0; o >>= 1) { if (tid < o) red[tid] += red[tid + o]; __syncthreads(); }
    sm = red[0]; __syncthreads();

    float s2 = 0.0f;
    for (int i = tid; i < NS; i += 512) {
        float m = mask[b * NS + i];
        float a = sc[i] / sm * m;
        att[i] = a; s2 += a;
    }
    red[tid] = s2; __syncthreads();
    for (int o = 256; o > 0; o >>= 1) { if (tid < o) red[tid] += red[tid + o]; __syncthreads(); }
    s2 = red[0]; __syncthreads();
    float inv = 1.0f / (s2 + 1e-10f);
    for (int i = tid; i < NS; i += 512) {
        float a = att[i] * inv;
        att[i] = a;
        g_attn[b * NS + i] = a;
        if (full) {
            out[OFF_AT + b * NS + i] = a;
            out[OFF_CV + b * NS + i] = cov[b * NS + i] + a;
        }
    }
    __syncthreads();

    {
        float a0 = 0.f, a1 = 0.f, a2 = 0.f, a3 = 0.f;
        const float* mbb = MB + (size_t)b * NS * NM + tid;
#pragma unroll 4
        for (int s = 0; s < NS; s += 4) {
            a0 += att[s]     * mbb[(size_t)s * NM];
            a1 += att[s + 1] * mbb[(size_t)(s + 1) * NM];
            a2 += att[s + 2] * mbb[(size_t)(s + 2) * NM];
            a3 += att[s + 3] * mbb[(size_t)(s + 3) * NM];
        }
        float a = (a0 + a1) + (a2 + a3);
        wcs[tid] = a;
        g_cat[b * (NM + NH) + tid] = a;
        if (full) out[OFF_WC + b * NM + tid] = a;
    }
    __syncthreads();

    int yb = y[b];
    float ps = 0.0f;
    for (int i = tid; i < NM + NH + NE; i += 512) {
        float xv = (i < NM) ? wcs[i]
                 : (i < NM + NH) ? g_h1[b * NH + (i - NM)]
                 : emb_W[(size_t)yb * NE + (i - NM - NH)];
        ps += pgen_W[i] * xv;
    }
    red[tid] = ps; __syncthreads();
    for (int o = 256; o > 0; o >>= 1) { if (tid < o) red[tid] += red[tid + o]; __syncthreads(); }
    if (tid == 0) {
        float p = sigmoidf_(red[0] + pgen_b[0]);
        g_pgen[b] = p;
        if (full) out[OFF_PG + b] = p;
    }
}

// ---------------------------------------------------------------------------
// K4a: vocab logits on tcgen05. D[128 vocab, 128 pad-b] = W2tile @ hidp^T.
// Epilogue: smem tile + simple column sums; g_logits in [b][v] layout.
// (validated round 13)
// ---------------------------------------------------------------------------
#define K4_A_OFF 1024
#define K4_B_OFF (1024 + 3 * 16384)
#define K4_SMEM  (1024 + 6 * 16384)   // 99328
#define ES_LD 65

__global__ __launch_bounds__(128, 1)
void k4a_tc(const float* __restrict__ W2, const float* __restrict__ b2)
{
    extern __shared__ char smem[];
    int tid = threadIdx.x, wid = tid >> 5;
    int vBase = blockIdx.x * 128;
    const int NT = NH / 32;   // 16 chunks

    auto loadc = [&](int u) {
        int s = u % 3;
        int k0 = u * 32;
        char* abase = smem + K4_A_OFF + s * 16384;
        char* bbase = smem + K4_B_OFF + s * 16384;
#pragma unroll
        for (int i = 0; i < 8; i++) {
            int idx = tid + i * 128;
            int row = idx >> 3, c = idx & 7;
            uint32_t boff = row * 128 + c * 16;
            uint32_t sw = boff ^ ((boff >> 3) & 0x70);
            int vr = vBase + row;
            cpa16p((float*)(abase + sw), &W2[(size_t)vr * NH + k0 + c * 4], vr < NV);
        }
#pragma unroll
        for (int i = 0; i < 8; i++) {
            int idx = tid + i * 128;
            int row = idx >> 3, c = idx & 7;
            uint32_t boff = row * 128 + c * 16;
            uint32_t sw = boff ^ ((boff >> 3) & 0x70);
            cpa16((float*)(bbase + sw), &g_hidp[(size_t)row * NH + k0 + c * 4]);
        }
        CP_COMMIT();
    };

#if USE_TCGEN05
    uint32_t sb = smem_u32(smem);
    if (wid == 0) { TCG_ALLOC(sb, 128); TCG_RELQ(); }
    if (tid == 0) { MB_INIT(sb + 8, 1); MB_INIT(sb + 16, 1); MB_INIT(sb + 24, 1); }
    __syncthreads();
    uint32_t tmem;
    asm volatile("ld.shared.b32 %0, [%1];" : "=r"(tmem) : "r"(sb));

    loadc(0); loadc(1); loadc(2);

    for (int t = 0; t < NT; t++) {
        if (t <= NT - 3) CP_WAIT2();
        else if (t == NT - 2) CP_WAIT1();
        else CP_WAIT0();
        FENCE_PA();
        __syncthreads();
        if (wid == 0) {
            TCG_FENCE_AFTER();
            if (elect1()) {
                int s = t % 3;
                uint64_t ad = mk_desc(sb + K4_A_OFF + s * 16384);
                uint64_t bd = mk_desc(sb + K4_B_OFF + s * 16384);
#pragma unroll
                for (int k = 0; k < 4; k++)
                    tcg_mma_tf32(tmem, ad + k * 2, bd + k * 2, K2_IDESC, !(t == 0 && k == 0));
                TCG_COMMIT(sb + 8 + (t % 3) * 8);
            }
        }
        int u = t + 3;
        if (u < NT) {
            mb_wait(sb + 8 + (u % 3) * 8, ((u / 3) - 1) & 1);
            loadc(u);
        }
    }
    mb_wait(sb + 8, 1);
    TCG_FENCE_AFTER();
    __syncthreads();

    float* es = (float*)(smem + K4_A_OFF);
    int v = vBase + tid;
    bool valid = (v < NV);
    float bias = valid ? b2[v] : 0.0f;
    {
        uint32_t d0[32];
        TCG_LD_X32(d0, tmem);
        TCG_WAIT_LD();
#pragma unroll
        for (int j = 0; j < 32; j++)
            es[tid * ES_LD + j] = valid ? expf(__uint_as_float(d0[j]) + bias) : 0.0f;
    }
    {
        uint32_t d1[32];
        TCG_LD_X32(d1, tmem + 32);
        TCG_WAIT_LD();
#pragma unroll
        for (int j = 0; j < 32; j++)
            es[tid * ES_LD + 32 + j] = valid ? expf(__uint_as_float(d1[j]) + bias) : 0.0f;
    }
    TCG_FENCE_BEFORE();
    __syncthreads();

    if (tid < 64) {
        float s = 0.0f;
#pragma unroll 8
        for (int r = 0; r < 128; r++) s += es[r * ES_LD + tid];
        atomicAdd(&g_sumexp[tid], s);
    }
    if (valid) {
#pragma unroll 4
        for (int b = 0; b < NB; b++)
            g_logits[(size_t)b * NV + v] = es[tid * ES_LD + b];
    }
    __syncthreads();
    if (tid == 0) { MB_INVAL(sb + 8); MB_INVAL(sb + 16); MB_INVAL(sb + 24); }
    __syncthreads();
    if (wid == 0) TCG_DEALLOC(tmem, 128);

#else   // scalar fallback
    int v = vBase + tid;
    if (v < NV) {
        float bias = b2[v];
        float s[NB];
        for (int b = 0; b < NB; b++) {
            float acc = bias;
            for (int k = 0; k < NH; k++)
                acc += W2[(size_t)v * NH + k] * g_hidp[(size_t)b * NH + k];
            s[b] = expf(acc);
            g_logits[(size_t)b * NV + v] = s[b];
        }
        for (int b = 0; b < NB; b++) atomicAdd(&g_sumexp[b], s[b]);
    }
#endif
}

// ---------------------------------------------------------------------------
// K4b: normalize + write final vocab part. grid=(64, 8), 256 thr.
// ---------------------------------------------------------------------------
#define VCHUNK 6250
__global__ void k4b_norm(float* __restrict__ out)
{
    int b = blockIdx.x, ch = blockIdx.y, tid = threadIdx.x;
    float scale = g_pgen[b] / g_sumexp[b];
    const float* lg = &g_logits[(size_t)b * NV];
    float* orow = out + (size_t)b * NVO;
    int v0 = ch * VCHUNK;
    for (int v = v0 + tid * 2; v < v0 + VCHUNK; v += 512) {
        float2 e = *(const float2*)&lg[v];
        e.x *= scale; e.y *= scale;
        *(float2*)&orow[v] = e;
    }
    if (ch == 0) {
        for (int v = NV + tid; v < NVO; v += 256) orow[v] = 0.0f;
    }
}

// ---------------------------------------------------------------------------
// K4c: OOV pointer scatter. grid=64, 400 thr.
// ---------------------------------------------------------------------------
__global__ void k4c_scatter(const int* __restrict__ src_oov, float* __restrict__ out)
{
    int b = blockIdx.x, s = threadIdx.x;
    float q = 1.0f - g_pgen[b];
    float* orow = out + (size_t)b * NVO;
    atomicAdd(&orow[src_oov[b * NS + s]], q * g_attn[b * NS + s]);
}

// ---------------------------------------------------------------------------
extern "C" void kernel_launch(void* const* d_in, const int* in_sizes, int n_in,
                              void* d_out, int out_size)
{
    int sh = (n_in >= 23) ? 1 : 0;
    const int*   y        = (const int*)  d_in[0];
    const float* h0g      = (const float*)d_in[1];
    const float* MB       = (const float*)d_in[2];
    const float* mask     = (const float*)d_in[3];
    const int*   src_oov  = (const int*)  d_in[4 + sh];
    const float* cov      = (const float*)d_in[5 + sh];
    const float* emb_W    = (const float*)d_in[6 + sh];
    const float* Wih      = (const float*)d_in[7 + sh];
    const float* Whh      = (const float*)d_in[8 + sh];
    const float* bih      = (const float*)d_in[9 + sh];
    const float* bhh      = (const float*)d_in[10 + sh];
    const float* Wm       = (const float*)d_in[11 + sh];
    const float* Wd       = (const float*)d_in[12 + sh];
    const float* bd       = (const float*)d_in[13 + sh];
    const float* Wc       = (const float*)d_in[14 + sh];
    const float* av       = (const float*)d_in[15 + sh];
    const float* pgen_W   = (const float*)d_in[16 + sh];
    const float* pgen_b   = (const float*)d_in[17 + sh];
    const float* vd1_W    = (const float*)d_in[18 + sh];
    const float* vd1_b    = (const float*)d_in[19 + sh];
    const float* W2       = (const float*)d_in[20 + sh];
    const float* b2       = (const float*)d_in[21 + sh];
    float* out = (float*)d_out;

    float *p_h1, *p_dec, *p_cat, *p_hidp;
    cudaGetSymbolAddress((void**)&p_h1,   g_h1);
    cudaGetSymbolAddress((void**)&p_dec,  g_dec);
    cudaGetSymbolAddress((void**)&p_cat,  g_cat);
    cudaGetSymbolAddress((void**)&p_hidp, g_hidp);

    cudaFuncSetAttribute(k2_tc,  cudaFuncAttributeMaxDynamicSharedMemorySize, K2_SMEM);
    cudaFuncSetAttribute(k4a_tc, cudaFuncAttributeMaxDynamicSharedMemorySize, K4_SMEM);

    // gi (blocks 0..23) and gh (blocks 24..47) fused into one launch
    k1a_gru_gemms<<<48, 256, GEMM_DYN_SMEM>>>(y, emb_W, h0g, Wih, bih, Whh, bhh);

    k1b_combine<<<NB, 512>>>(h0g, out, out_size);

    gemm_nt<512><<<NH / 64, 256, GEMM_DYN_SMEM>>>(p_h1, Wd, bd, p_dec, NH);  // dec_feat

    dim3 g2(NM / 128, (NB * NS) / 128);   // (4, 200)
    k2_tc<<<g2, 128, K2_SMEM>>>(MB, Wm, Wc, av, cov);

    k3_attn<<<NB, 512>>>(MB, mask, cov, y, emb_W, pgen_W, pgen_b, out, out_size);

    gemm_nt<1024><<<NH / 64, 256, GEMM_DYN_SMEM>>>(p_cat, vd1_W, vd1_b, p_hidp, NH); // vd1

    k4a_tc<<<(NV + 127) / 128, 128, K4_SMEM>>>(W2, b2);

    dim3 g4b(NB, 8);
    k4b_norm<<<g4b, 256>>>(out);
    k4c_scatter<<<NB, NS>>>(src_oov, out);
}